// round 1
// baseline (speedup 1.0000x reference)
#include <cuda_runtime.h>
#include <math.h>

#define TSEQ 1536
#define HID  2880
#define NHEAD 64
#define NKVH  8
#define DH    64
#define QC   (NHEAD*DH)        /* 4096 */
#define KVC  (NKVH*DH)         /* 512  */
#define NTOT (QC + 2*KVC)      /* 5120 */
#define NOUT 2880

// Scratch (allocation-free rule: device globals)
__device__ float g_Q[TSEQ*QC];
__device__ float g_K[TSEQ*KVC];
__device__ float g_V[TSEQ*KVC];
__device__ float g_Y[TSEQ*QC];

#define BM 128
#define BN 128
#define BK 8

// log2(150000)/32
#define L2THETA_OVER_32 0.53733134f

// ---------------------------------------------------------------------------
// Fused QKV GEMM: [x (1536x2880)] @ [Wq|Wk|Wv] + bias, with RoPE applied to
// the Q and K regions in the epilogue. Column regions: [0,4096)=Q,
// [4096,4608)=K, [4608,5120)=V. BN=128 divides every region boundary, so a
// block lives entirely in one region. Note ld(W) == ld(out) in every region.
// ---------------------------------------------------------------------------
__global__ __launch_bounds__(256) void qkv_gemm(
    const float* __restrict__ x,
    const float* __restrict__ Wq, const float* __restrict__ bq,
    const float* __restrict__ Wk, const float* __restrict__ bk,
    const float* __restrict__ Wv, const float* __restrict__ bv,
    const int*   __restrict__ positions)
{
    __shared__ float As[BK][BM];
    __shared__ float Bs[BK][BN];

    const int tid = threadIdx.x;
    const int m0  = blockIdx.y * BM;
    const int n0  = blockIdx.x * BN;

    const float* W;  const float* bias;  float* outp;
    int ldout, nloc0, do_rope;
    if (n0 < QC)            { W = Wq; bias = bq; outp = g_Q; ldout = QC;  nloc0 = n0;            do_rope = 1; }
    else if (n0 < QC + KVC) { W = Wk; bias = bk; outp = g_K; ldout = KVC; nloc0 = n0 - QC;       do_rope = 1; }
    else                    { W = Wv; bias = bv; outp = g_V; ldout = KVC; nloc0 = n0 - QC - KVC; do_rope = 0; }

    const int ar = tid >> 1;            // 0..127
    const int ac = (tid & 1) * 4;       // 0 or 4
    const int br = tid >> 5;            // 0..7
    const int bc = (tid & 31) * 4;      // 0..124

    const int tx = tid & 15;
    const int ty = tid >> 4;

    float acc[8][8];
    #pragma unroll
    for (int i = 0; i < 8; i++)
        #pragma unroll
        for (int j = 0; j < 8; j++) acc[i][j] = 0.f;

    for (int k0 = 0; k0 < HID; k0 += BK) {
        float4 av  = *(const float4*)(x + (long)(m0 + ar) * HID + k0 + ac);
        float4 bv4 = *(const float4*)(W + (long)(k0 + br) * ldout + nloc0 + bc);
        __syncthreads();
        As[ac + 0][ar] = av.x; As[ac + 1][ar] = av.y;
        As[ac + 2][ar] = av.z; As[ac + 3][ar] = av.w;
        *(float4*)&Bs[br][bc] = bv4;
        __syncthreads();
        #pragma unroll
        for (int k = 0; k < BK; k++) {
            float a[8], b[8];
            *(float4*)&a[0] = *(const float4*)&As[k][ty * 8];
            *(float4*)&a[4] = *(const float4*)&As[k][ty * 8 + 4];
            *(float4*)&b[0] = *(const float4*)&Bs[k][tx * 8];
            *(float4*)&b[4] = *(const float4*)&Bs[k][tx * 8 + 4];
            #pragma unroll
            for (int i = 0; i < 8; i++)
                #pragma unroll
                for (int j = 0; j < 8; j++)
                    acc[i][j] += a[i] * b[j];
        }
    }

    // Epilogue: bias + RoPE (pairs are adjacent even/odd columns; thread's 8
    // contiguous columns start at an even index, so pairs stay in-thread)
    #pragma unroll
    for (int i = 0; i < 8; i++) {
        const int t = m0 + ty * 8 + i;
        float pos = 0.f;
        if (do_rope) pos = (float)positions[t];
        #pragma unroll
        for (int j = 0; j < 8; j += 2) {
            const int c = nloc0 + tx * 8 + j;
            float e  = acc[i][j]     + bias[c];
            float od = acc[i][j + 1] + bias[c + 1];
            if (do_rope) {
                const int ip = (c & (DH - 1)) >> 1;
                // inv_eff = 0.5*(f + f/32) = f * 0.515625 ; f = theta^(-ip/32)
                float inv_eff = 0.515625f * exp2f(-(float)ip * L2THETA_OVER_32);
                float ang = pos * (1.0f / 32.0f) * inv_eff;
                float sn, cs;
                __sincosf(ang, &sn, &cs);
                float e2 = e * cs - od * sn;
                od       = e * sn + od * cs;
                e = e2;
            }
            outp[(long)t * ldout + c]     = e;
            outp[(long)t * ldout + c + 1] = od;
        }
    }
}

// ---------------------------------------------------------------------------
// Sliding-window GQA attention. One block = (head, 128 queries); one thread
// per query. K/V streamed through SMEM in 64-key chunks; online softmax with
// q[64] and o[64] register-resident. SMEM reads are warp-broadcast.
// ---------------------------------------------------------------------------
__global__ __launch_bounds__(128) void attn_kernel(
    const int* __restrict__ is_slide_p, const int* __restrict__ win_p)
{
    const int h   = blockIdx.y;
    const int t0  = blockIdx.x * 128;
    const int tid = threadIdx.x;
    const int t   = t0 + tid;
    const int kvh = h >> 3;                 // GROUP = 8 (jnp.repeat -> h // 8)

    const int is_slide = is_slide_p[0];
    const int W        = win_p[0];

    __shared__ float Ks[64][64];
    __shared__ float Vs[64][64];

    float q[DH];
    #pragma unroll
    for (int d = 0; d < DH; d++) q[d] = g_Q[(long)t * QC + h * DH + d];

    float o[DH];
    #pragma unroll
    for (int d = 0; d < DH; d++) o[d] = 0.f;
    float m = -INFINITY, l = 0.f;

    const int blk_lo = is_slide ? max(0, t0 - W) : 0;
    const int blk_hi = is_slide ? (t0 + 127)     : (TSEQ - 1);
    const int my_lo  = is_slide ? max(0, t - W)  : 0;
    const int my_hi  = is_slide ? t              : (TSEQ - 1);

    const int c0 = (blk_lo / 64) * 64;

    for (int cs = c0; cs <= blk_hi; cs += 64) {
        __syncthreads();
        #pragma unroll
        for (int it = 0; it < 8; ++it) {
            int idx = it * 128 + tid;        // 0..1023
            int r   = idx >> 4;
            int c4  = (idx & 15) << 2;
            int s   = cs + r;
            float4 kv = make_float4(0.f, 0.f, 0.f, 0.f);
            float4 vv = make_float4(0.f, 0.f, 0.f, 0.f);
            if (s < TSEQ) {
                kv = *(const float4*)(g_K + (long)s * KVC + kvh * DH + c4);
                vv = *(const float4*)(g_V + (long)s * KVC + kvh * DH + c4);
            }
            *(float4*)&Ks[r][c4] = kv;
            *(float4*)&Vs[r][c4] = vv;
        }
        __syncthreads();

        const int ls = max(cs, my_lo) - cs;
        const int le = min(cs + 63, my_hi) - cs;
        for (int sl = ls; sl <= le; ++sl) {
            float sc = 0.f;
            #pragma unroll
            for (int d = 0; d < DH; d++) sc += q[d] * Ks[sl][d];
            sc *= 0.125f;                       // 1/sqrt(64)
            float mn    = fmaxf(m, sc);
            float p     = __expf(sc - mn);
            float alpha = __expf(m - mn);
            l = l * alpha + p;
            #pragma unroll
            for (int d = 0; d < DH; d++) o[d] = o[d] * alpha + p * Vs[sl][d];
            m = mn;
        }
    }

    const float inv = 1.f / l;
    #pragma unroll
    for (int d = 0; d < DH; d++) g_Y[(long)t * QC + h * DH + d] = o[d] * inv;
}

// ---------------------------------------------------------------------------
// Output projection: g_Y (1536x4096) @ Wo (4096x2880) + bo. N=2880 is not a
// multiple of 128 -> column guards (2880 % 4 == 0, so float4 loads are
// either fully in-range or fully out).
// ---------------------------------------------------------------------------
__global__ __launch_bounds__(256) void out_gemm(
    const float* __restrict__ Wo, const float* __restrict__ bo,
    float* __restrict__ out)
{
    __shared__ float As[BK][BM];
    __shared__ float Bs[BK][BN];

    const int tid = threadIdx.x;
    const int m0  = blockIdx.y * BM;
    const int n0  = blockIdx.x * BN;

    const int ar = tid >> 1;
    const int ac = (tid & 1) * 4;
    const int br = tid >> 5;
    const int bc = (tid & 31) * 4;
    const int tx = tid & 15;
    const int ty = tid >> 4;

    float acc[8][8];
    #pragma unroll
    for (int i = 0; i < 8; i++)
        #pragma unroll
        for (int j = 0; j < 8; j++) acc[i][j] = 0.f;

    for (int k0 = 0; k0 < QC; k0 += BK) {
        float4 av  = *(const float4*)(g_Y + (long)(m0 + ar) * QC + k0 + ac);
        float4 bv4 = make_float4(0.f, 0.f, 0.f, 0.f);
        if (n0 + bc < NOUT)
            bv4 = *(const float4*)(Wo + (long)(k0 + br) * NOUT + n0 + bc);
        __syncthreads();
        As[ac + 0][ar] = av.x; As[ac + 1][ar] = av.y;
        As[ac + 2][ar] = av.z; As[ac + 3][ar] = av.w;
        *(float4*)&Bs[br][bc] = bv4;
        __syncthreads();
        #pragma unroll
        for (int k = 0; k < BK; k++) {
            float a[8], b[8];
            *(float4*)&a[0] = *(const float4*)&As[k][ty * 8];
            *(float4*)&a[4] = *(const float4*)&As[k][ty * 8 + 4];
            *(float4*)&b[0] = *(const float4*)&Bs[k][tx * 8];
            *(float4*)&b[4] = *(const float4*)&Bs[k][tx * 8 + 4];
            #pragma unroll
            for (int i = 0; i < 8; i++)
                #pragma unroll
                for (int j = 0; j < 8; j++)
                    acc[i][j] += a[i] * b[j];
        }
    }

    #pragma unroll
    for (int i = 0; i < 8; i++) {
        const int t = m0 + ty * 8 + i;
        #pragma unroll
        for (int j = 0; j < 8; j++) {
            const int c = n0 + tx * 8 + j;
            if (c < NOUT)
                out[(long)t * NOUT + c] = acc[i][j] + bo[c];
        }
    }
}

// ---------------------------------------------------------------------------
extern "C" void kernel_launch(void* const* d_in, const int* in_sizes, int n_in,
                              void* d_out, int out_size)
{
    const float* x         = (const float*)d_in[0];
    const int*   positions = (const int*)  d_in[1];
    const float* Wq        = (const float*)d_in[2];
    const float* bq        = (const float*)d_in[3];
    const float* Wk        = (const float*)d_in[4];
    const float* bk        = (const float*)d_in[5];
    const float* Wv        = (const float*)d_in[6];
    const float* bv        = (const float*)d_in[7];
    const float* Wo        = (const float*)d_in[8];
    const float* bo        = (const float*)d_in[9];
    const int*   is_slide  = (const int*)  d_in[10];
    const int*   win       = (const int*)  d_in[11];

    dim3 g1(NTOT / BN, TSEQ / BM);               // (40, 12)
    qkv_gemm<<<g1, 256>>>(x, Wq, bq, Wk, bk, Wv, bv, positions);

    dim3 g2(TSEQ / 128, NHEAD);                  // (12, 64)
    attn_kernel<<<g2, 128>>>(is_slide, win);

    dim3 g3((NOUT + BN - 1) / BN, TSEQ / BM);    // (23, 12)
    out_gemm<<<g3, 256>>>(Wo, bo, (float*)d_out);
}

// round 3
// speedup vs baseline: 2.1497x; 2.1497x over previous
#include <cuda_runtime.h>
#include <math.h>
#include <stdint.h>

#define TSEQ 1536
#define HID  2880
#define NHEAD 64
#define NKVH  8
#define DH    64
#define QC   (NHEAD*DH)        /* 4096 */
#define KVC  (NKVH*DH)         /* 512  */
#define NTOT (QC + 2*KVC)      /* 5120 */
#define NOUT 2880
#define NOUT_PAD 2944          /* 23*128 */

#define L2THETA_OVER_32 0.53733134f

// ---------------- device-global scratch -------------------------------------
__device__ float g_Q[(size_t)TSEQ*QC];
__device__ float g_K[(size_t)TSEQ*KVC];
__device__ float g_V[(size_t)TSEQ*KVC];
__device__ float g_Y[(size_t)TSEQ*QC];
__device__ float g_WT[(size_t)NTOT*HID];        // qkv weights, [n][k]
__device__ float g_WoT[(size_t)NOUT_PAD*QC];    // out weights, [n][k], pad rows 0

// ---------------- helpers ----------------------------------------------------
__device__ __forceinline__ uint32_t tf32_bits(float x) {
    uint32_t u;
    asm("cvt.rna.tf32.f32 %0, %1;" : "=r"(u) : "f"(x));
    return u;
}
__device__ __forceinline__ float4 tf32x4(float4 v) {
    v.x = __uint_as_float(tf32_bits(v.x));
    v.y = __uint_as_float(tf32_bits(v.y));
    v.z = __uint_as_float(tf32_bits(v.z));
    v.w = __uint_as_float(tf32_bits(v.w));
    return v;
}
__device__ __forceinline__ void mma_tf32(float c[4], const uint32_t a[4], const uint32_t b[2]) {
    asm volatile(
        "mma.sync.aligned.m16n8k8.row.col.f32.tf32.tf32.f32 "
        "{%0,%1,%2,%3}, {%4,%5,%6,%7}, {%8,%9}, {%0,%1,%2,%3};"
        : "+f"(c[0]), "+f"(c[1]), "+f"(c[2]), "+f"(c[3])
        : "r"(a[0]), "r"(a[1]), "r"(a[2]), "r"(a[3]), "r"(b[0]), "r"(b[1]));
}

#define BK  32
#define PAD 36   /* floats per smem row: 32 data + 4 pad (keeps float4 align, kills conflicts) */

// ---------------- weight transposes -----------------------------------------
__global__ void transpose_qkv(const float* __restrict__ Wq,
                              const float* __restrict__ Wk,
                              const float* __restrict__ Wv)
{
    __shared__ float tile[32][33];
    const int n0 = blockIdx.x * 32, k0 = blockIdx.y * 32;
    const float* src; int ld, nb;
    if (n0 < QC)            { src = Wq; ld = QC;  nb = n0; }
    else if (n0 < QC + KVC) { src = Wk; ld = KVC; nb = n0 - QC; }
    else                    { src = Wv; ld = KVC; nb = n0 - QC - KVC; }
    const int tx = threadIdx.x, ty = threadIdx.y;
    #pragma unroll
    for (int i = 0; i < 32; i += 8)
        tile[ty + i][tx] = src[(size_t)(k0 + ty + i) * ld + nb + tx];
    __syncthreads();
    #pragma unroll
    for (int i = 0; i < 32; i += 8)
        g_WT[(size_t)(n0 + ty + i) * HID + k0 + tx] = tile[tx][ty + i];
}

__global__ void transpose_wo(const float* __restrict__ Wo)
{
    __shared__ float tile[32][33];
    const int n0 = blockIdx.x * 32, k0 = blockIdx.y * 32;
    const int tx = threadIdx.x, ty = threadIdx.y;
    #pragma unroll
    for (int i = 0; i < 32; i += 8)
        tile[ty + i][tx] = Wo[(size_t)(k0 + ty + i) * NOUT + n0 + tx];
    __syncthreads();
    #pragma unroll
    for (int i = 0; i < 32; i += 8)
        g_WoT[(size_t)(n0 + ty + i) * QC + k0 + tx] = tile[tx][ty + i];
}

// ---------------- shared GEMM mainloop (tf32 mma.sync) ----------------------
// Computes acc[mt][nt][4] for a 128x128 C tile = A[128 x K] * B[128 x K]^T.
// A = Ag rows m0.., lda=K ; B = Bg rows n0.., ldb=K. 8 warps: warp_m=wid&3
// (32 rows), warp_n=wid>>2 (64 cols). Per warp: 2 m-tiles x 8 n-tiles.
__device__ __forceinline__ void gemm_mainloop(
    const float* __restrict__ Ag, const float* __restrict__ Bg,
    int m0, int n0, int K,
    float (&acc)[2][8][4],
    float (*As)[PAD], float (*Bs)[PAD])
{
    const int tid  = threadIdx.x;
    const int lane = tid & 31;
    const int wid  = tid >> 5;
    const int warp_m = wid & 3, warp_n = wid >> 2;
    const int gid = lane >> 2, tig = lane & 3;

    const int r  = tid >> 1;            // 0..127  (load row)
    const int c4 = (tid & 1) * 4;       // 0 or 4 : two threads per row cover 8 floats? no
    (void)c4;

    // loader mapping: 256 threads * 4 float4 = 1024 float4 = 128 rows * 8 chunks
    float4 ra[4], rb[4];
    #pragma unroll
    for (int i = 0; i < 4; i++) {
        int idx = i * 256 + tid, rr = idx >> 3, f = (idx & 7) * 4;
        ra[i] = *(const float4*)(Ag + (size_t)(m0 + rr) * K + f);
        rb[i] = *(const float4*)(Bg + (size_t)(n0 + rr) * K + f);
    }
    #pragma unroll
    for (int i = 0; i < 4; i++) {
        int idx = i * 256 + tid, rr = idx >> 3, f = (idx & 7) * 4;
        *(float4*)&As[rr][f] = tf32x4(ra[i]);
        *(float4*)&Bs[rr][f] = tf32x4(rb[i]);
    }
    __syncthreads();

    const int NK = K / BK;
    for (int kc = 0; kc < NK; kc++) {
        if (kc + 1 < NK) {
            const int k0 = (kc + 1) * BK;
            #pragma unroll
            for (int i = 0; i < 4; i++) {
                int idx = i * 256 + tid, rr = idx >> 3, f = (idx & 7) * 4;
                ra[i] = *(const float4*)(Ag + (size_t)(m0 + rr) * K + k0 + f);
                rb[i] = *(const float4*)(Bg + (size_t)(n0 + rr) * K + k0 + f);
            }
        }
        #pragma unroll
        for (int ks = 0; ks < BK; ks += 8) {
            uint32_t af[2][4], bf[8][2];
            #pragma unroll
            for (int mt = 0; mt < 2; mt++) {
                const int rb_ = warp_m * 32 + mt * 16 + gid;
                af[mt][0] = __float_as_uint(As[rb_    ][ks + tig]);
                af[mt][1] = __float_as_uint(As[rb_ + 8][ks + tig]);
                af[mt][2] = __float_as_uint(As[rb_    ][ks + tig + 4]);
                af[mt][3] = __float_as_uint(As[rb_ + 8][ks + tig + 4]);
            }
            #pragma unroll
            for (int nt = 0; nt < 8; nt++) {
                const int nn = warp_n * 64 + nt * 8 + gid;
                bf[nt][0] = __float_as_uint(Bs[nn][ks + tig]);
                bf[nt][1] = __float_as_uint(Bs[nn][ks + tig + 4]);
            }
            #pragma unroll
            for (int mt = 0; mt < 2; mt++)
                #pragma unroll
                for (int nt = 0; nt < 8; nt++)
                    mma_tf32(acc[mt][nt], af[mt], bf[nt]);
        }
        __syncthreads();
        if (kc + 1 < NK) {
            #pragma unroll
            for (int i = 0; i < 4; i++) {
                int idx = i * 256 + tid, rr = idx >> 3, f = (idx & 7) * 4;
                *(float4*)&As[rr][f] = tf32x4(ra[i]);
                *(float4*)&Bs[rr][f] = tf32x4(rb[i]);
            }
            __syncthreads();
        }
    }
    (void)r;
}

// ---------------- QKV projection (+bias, +RoPE) ------------------------------
__global__ __launch_bounds__(256) void qkv_mma(
    const float* __restrict__ x, const int* __restrict__ positions,
    const float* __restrict__ bq, const float* __restrict__ bk,
    const float* __restrict__ bv)
{
    __shared__ float As[128][PAD];
    __shared__ float Bs[128][PAD];

    const int tid  = threadIdx.x;
    const int lane = tid & 31;
    const int wid  = tid >> 5;
    const int warp_m = wid & 3, warp_n = wid >> 2;
    const int gid = lane >> 2, tig = lane & 3;
    const int m0 = blockIdx.y * 128, n0 = blockIdx.x * 128;

    const float* bias; float* outp; int ldout, nloc0, do_rope;
    if (n0 < QC)            { bias = bq; outp = g_Q; ldout = QC;  nloc0 = n0;            do_rope = 1; }
    else if (n0 < QC + KVC) { bias = bk; outp = g_K; ldout = KVC; nloc0 = n0 - QC;       do_rope = 1; }
    else                    { bias = bv; outp = g_V; ldout = KVC; nloc0 = n0 - QC - KVC; do_rope = 0; }

    float acc[2][8][4];
    #pragma unroll
    for (int a = 0; a < 2; a++)
        #pragma unroll
        for (int b = 0; b < 8; b++)
            #pragma unroll
            for (int d = 0; d < 4; d++) acc[a][b][d] = 0.f;

    gemm_mainloop(x, g_WT, m0, n0, HID, acc, As, Bs);

    // precompute RoPE inv_eff per n-tile pair (2 cols per thread -> 1 ip per nt)
    #pragma unroll
    for (int mt = 0; mt < 2; mt++) {
        const int t_lo = m0 + warp_m * 32 + mt * 16 + gid;
        const int t_hi = t_lo + 8;
        float pos_lo = 0.f, pos_hi = 0.f;
        if (do_rope) { pos_lo = (float)positions[t_lo]; pos_hi = (float)positions[t_hi]; }
        #pragma unroll
        for (int nt = 0; nt < 8; nt++) {
            const int c = nloc0 + warp_n * 64 + nt * 8 + 2 * tig;
            const float b0 = bias[c], b1 = bias[c + 1];
            float v0 = acc[mt][nt][0] + b0, v1 = acc[mt][nt][1] + b1;  // row t_lo
            float v2 = acc[mt][nt][2] + b0, v3 = acc[mt][nt][3] + b1;  // row t_hi
            if (do_rope) {
                const int ip = (c & (DH - 1)) >> 1;
                const float inv_eff = 0.515625f * exp2f(-(float)ip * L2THETA_OVER_32);
                float s, co;
                __sincosf(pos_lo * (1.0f / 32.0f) * inv_eff, &s, &co);
                float e = v0 * co - v1 * s; v1 = v0 * s + v1 * co; v0 = e;
                __sincosf(pos_hi * (1.0f / 32.0f) * inv_eff, &s, &co);
                e = v2 * co - v3 * s; v3 = v2 * s + v3 * co; v2 = e;
            }
            *(float2*)(outp + (size_t)t_lo * ldout + c) = make_float2(v0, v1);
            *(float2*)(outp + (size_t)t_hi * ldout + c) = make_float2(v2, v3);
        }
    }
}

// ---------------- output projection (+bias) ----------------------------------
__global__ __launch_bounds__(256) void out_mma(
    const float* __restrict__ bo, float* __restrict__ out)
{
    __shared__ float As[128][PAD];
    __shared__ float Bs[128][PAD];

    const int tid  = threadIdx.x;
    const int lane = tid & 31;
    const int wid  = tid >> 5;
    const int warp_m = wid & 3, warp_n = wid >> 2;
    const int gid = lane >> 2, tig = lane & 3;
    const int m0 = blockIdx.y * 128, n0 = blockIdx.x * 128;

    float acc[2][8][4];
    #pragma unroll
    for (int a = 0; a < 2; a++)
        #pragma unroll
        for (int b = 0; b < 8; b++)
            #pragma unroll
            for (int d = 0; d < 4; d++) acc[a][b][d] = 0.f;

    gemm_mainloop(g_Y, g_WoT, m0, n0, QC, acc, As, Bs);

    #pragma unroll
    for (int mt = 0; mt < 2; mt++) {
        const int t_lo = m0 + warp_m * 32 + mt * 16 + gid;
        const int t_hi = t_lo + 8;
        #pragma unroll
        for (int nt = 0; nt < 8; nt++) {
            const int c = n0 + warp_n * 64 + nt * 8 + 2 * tig;
            if (c < NOUT) {
                const float b0 = bo[c], b1 = bo[c + 1];
                *(float2*)(out + (size_t)t_lo * NOUT + c) =
                    make_float2(acc[mt][nt][0] + b0, acc[mt][nt][1] + b1);
                *(float2*)(out + (size_t)t_hi * NOUT + c) =
                    make_float2(acc[mt][nt][2] + b0, acc[mt][nt][3] + b1);
            }
        }
    }
}

// ---------------- sliding-window GQA attention (fp32) ------------------------
__global__ __launch_bounds__(128) void attn_kernel(
    const int* __restrict__ is_slide_p, const int* __restrict__ win_p)
{
    const int h   = blockIdx.y;
    const int t0  = blockIdx.x * 128;
    const int tid = threadIdx.x;
    const int t   = t0 + tid;
    const int kvh = h >> 3;

    const int is_slide = is_slide_p[0];
    const int W        = win_p[0];

    __shared__ float Ks[64][64];
    __shared__ float Vs[64][64];

    float q[DH];
    #pragma unroll
    for (int d = 0; d < DH; d++) q[d] = g_Q[(size_t)t * QC + h * DH + d];

    float o[DH];
    #pragma unroll
    for (int d = 0; d < DH; d++) o[d] = 0.f;
    float m = -INFINITY, l = 0.f;

    const int blk_lo = is_slide ? max(0, t0 - W) : 0;
    const int blk_hi = is_slide ? (t0 + 127)     : (TSEQ - 1);
    const int my_lo  = is_slide ? max(0, t - W)  : 0;
    const int my_hi  = is_slide ? t              : (TSEQ - 1);

    const int c0 = (blk_lo / 64) * 64;

    for (int cs = c0; cs <= blk_hi; cs += 64) {
        __syncthreads();
        #pragma unroll
        for (int it = 0; it < 8; ++it) {
            int idx = it * 128 + tid;
            int r   = idx >> 4;
            int cc  = (idx & 15) << 2;
            int s   = cs + r;
            float4 kv = make_float4(0.f, 0.f, 0.f, 0.f);
            float4 vv = make_float4(0.f, 0.f, 0.f, 0.f);
            if (s < TSEQ) {
                kv = *(const float4*)(g_K + (size_t)s * KVC + kvh * DH + cc);
                vv = *(const float4*)(g_V + (size_t)s * KVC + kvh * DH + cc);
            }
            *(float4*)&Ks[r][cc] = kv;
            *(float4*)&Vs[r][cc] = vv;
        }
        __syncthreads();

        const int ls = max(cs, my_lo) - cs;
        const int le = min(cs + 63, my_hi) - cs;
        for (int sl = ls; sl <= le; ++sl) {
            float sc = 0.f;
            #pragma unroll
            for (int d = 0; d < DH; d++) sc += q[d] * Ks[sl][d];
            sc *= 0.125f;
            float mn    = fmaxf(m, sc);
            float p     = __expf(sc - mn);
            float alpha = __expf(m - mn);
            l = l * alpha + p;
            #pragma unroll
            for (int d = 0; d < DH; d++) o[d] = o[d] * alpha + p * Vs[sl][d];
            m = mn;
        }
    }

    const float inv = 1.f / l;
    #pragma unroll
    for (int d = 0; d < DH; d++) g_Y[(size_t)t * QC + h * DH + d] = o[d] * inv;
}

// ---------------------------------------------------------------------------
extern "C" void kernel_launch(void* const* d_in, const int* in_sizes, int n_in,
                              void* d_out, int out_size)
{
    const float* x         = (const float*)d_in[0];
    const int*   positions = (const int*)  d_in[1];
    const float* Wq        = (const float*)d_in[2];
    const float* bq        = (const float*)d_in[3];
    const float* Wk        = (const float*)d_in[4];
    const float* bk        = (const float*)d_in[5];
    const float* Wv        = (const float*)d_in[6];
    const float* bv        = (const float*)d_in[7];
    const float* Wo        = (const float*)d_in[8];
    const float* bo        = (const float*)d_in[9];
    const int*   is_slide  = (const int*)  d_in[10];
    const int*   win       = (const int*)  d_in[11];

    dim3 tb(32, 8);
    transpose_qkv<<<dim3(NTOT / 32, HID / 32), tb>>>(Wq, Wk, Wv);
    transpose_wo <<<dim3(NOUT / 32, QC / 32),  tb>>>(Wo);

    qkv_mma<<<dim3(NTOT / 128, TSEQ / 128), 256>>>(x, positions, bq, bk, bv);

    attn_kernel<<<dim3(TSEQ / 128, NHEAD), 128>>>(is_slide, win);

    out_mma<<<dim3(NOUT_PAD / 128, TSEQ / 128), 256>>>(bo, (float*)d_out);
}

// round 4
// speedup vs baseline: 3.5109x; 1.6332x over previous
#include <cuda_runtime.h>
#include <math.h>
#include <stdint.h>

#define TSEQ 1536
#define HID  2880
#define NHEAD 64
#define NKVH  8
#define DH    64
#define QC   (NHEAD*DH)        /* 4096 */
#define KVC  (NKVH*DH)         /* 512  */
#define NTOT (QC + 2*KVC)      /* 5120 */
#define NOUT 2880
#define NOUT_PAD 2944          /* 23*128 */

#define L2THETA_OVER_32 0.53733134f

// ---------------- device-global scratch -------------------------------------
__device__ float g_Q[(size_t)TSEQ*QC];
__device__ float g_K[(size_t)TSEQ*KVC];
__device__ float g_V[(size_t)TSEQ*KVC];
__device__ float g_Y[(size_t)TSEQ*QC];
__device__ float g_WT[(size_t)NTOT*HID];        // qkv weights, [n][k]
__device__ float g_WoT[(size_t)NOUT_PAD*QC];    // out weights, [n][k], pad rows 0

// ---------------- helpers ----------------------------------------------------
__device__ __forceinline__ uint32_t tf32_bits(float x) {
    uint32_t u;
    asm("cvt.rna.tf32.f32 %0, %1;" : "=r"(u) : "f"(x));
    return u;
}
__device__ __forceinline__ float4 tf32x4(float4 v) {
    v.x = __uint_as_float(tf32_bits(v.x));
    v.y = __uint_as_float(tf32_bits(v.y));
    v.z = __uint_as_float(tf32_bits(v.z));
    v.w = __uint_as_float(tf32_bits(v.w));
    return v;
}
__device__ __forceinline__ void mma_tf32(float c[4], const uint32_t a[4], const uint32_t b[2]) {
    asm volatile(
        "mma.sync.aligned.m16n8k8.row.col.f32.tf32.tf32.f32 "
        "{%0,%1,%2,%3}, {%4,%5,%6,%7}, {%8,%9}, {%0,%1,%2,%3};"
        : "+f"(c[0]), "+f"(c[1]), "+f"(c[2]), "+f"(c[3])
        : "r"(a[0]), "r"(a[1]), "r"(a[2]), "r"(a[3]), "r"(b[0]), "r"(b[1]));
}

#define BK  32
#define PAD 36

// ---------------- weight transposes -----------------------------------------
__global__ void transpose_qkv(const float* __restrict__ Wq,
                              const float* __restrict__ Wk,
                              const float* __restrict__ Wv)
{
    __shared__ float tile[32][33];
    const int n0 = blockIdx.x * 32, k0 = blockIdx.y * 32;
    const float* src; int ld, nb;
    if (n0 < QC)            { src = Wq; ld = QC;  nb = n0; }
    else if (n0 < QC + KVC) { src = Wk; ld = KVC; nb = n0 - QC; }
    else                    { src = Wv; ld = KVC; nb = n0 - QC - KVC; }
    const int tx = threadIdx.x, ty = threadIdx.y;
    #pragma unroll
    for (int i = 0; i < 32; i += 8)
        tile[ty + i][tx] = src[(size_t)(k0 + ty + i) * ld + nb + tx];
    __syncthreads();
    #pragma unroll
    for (int i = 0; i < 32; i += 8)
        g_WT[(size_t)(n0 + ty + i) * HID + k0 + tx] = tile[tx][ty + i];
}

__global__ void transpose_wo(const float* __restrict__ Wo)
{
    __shared__ float tile[32][33];
    const int n0 = blockIdx.x * 32, k0 = blockIdx.y * 32;
    const int tx = threadIdx.x, ty = threadIdx.y;
    #pragma unroll
    for (int i = 0; i < 32; i += 8)
        tile[ty + i][tx] = Wo[(size_t)(k0 + ty + i) * NOUT + n0 + tx];
    __syncthreads();
    #pragma unroll
    for (int i = 0; i < 32; i += 8)
        g_WoT[(size_t)(n0 + ty + i) * QC + k0 + tx] = tile[tx][ty + i];
}

// ---------------- shared GEMM mainloop (tf32 mma.sync) ----------------------
__device__ __forceinline__ void gemm_mainloop(
    const float* __restrict__ Ag, const float* __restrict__ Bg,
    int m0, int n0, int K,
    float (&acc)[2][8][4],
    float (*As)[PAD], float (*Bs)[PAD])
{
    const int tid  = threadIdx.x;
    const int lane = tid & 31;
    const int wid  = tid >> 5;
    const int warp_m = wid & 3, warp_n = wid >> 2;
    const int gid = lane >> 2, tig = lane & 3;

    float4 ra[4], rb[4];
    #pragma unroll
    for (int i = 0; i < 4; i++) {
        int idx = i * 256 + tid, rr = idx >> 3, f = (idx & 7) * 4;
        ra[i] = *(const float4*)(Ag + (size_t)(m0 + rr) * K + f);
        rb[i] = *(const float4*)(Bg + (size_t)(n0 + rr) * K + f);
    }
    #pragma unroll
    for (int i = 0; i < 4; i++) {
        int idx = i * 256 + tid, rr = idx >> 3, f = (idx & 7) * 4;
        *(float4*)&As[rr][f] = tf32x4(ra[i]);
        *(float4*)&Bs[rr][f] = tf32x4(rb[i]);
    }
    __syncthreads();

    const int NK = K / BK;
    for (int kc = 0; kc < NK; kc++) {
        if (kc + 1 < NK) {
            const int k0 = (kc + 1) * BK;
            #pragma unroll
            for (int i = 0; i < 4; i++) {
                int idx = i * 256 + tid, rr = idx >> 3, f = (idx & 7) * 4;
                ra[i] = *(const float4*)(Ag + (size_t)(m0 + rr) * K + k0 + f);
                rb[i] = *(const float4*)(Bg + (size_t)(n0 + rr) * K + k0 + f);
            }
        }
        #pragma unroll
        for (int ks = 0; ks < BK; ks += 8) {
            uint32_t af[2][4], bf[8][2];
            #pragma unroll
            for (int mt = 0; mt < 2; mt++) {
                const int rb_ = warp_m * 32 + mt * 16 + gid;
                af[mt][0] = __float_as_uint(As[rb_    ][ks + tig]);
                af[mt][1] = __float_as_uint(As[rb_ + 8][ks + tig]);
                af[mt][2] = __float_as_uint(As[rb_    ][ks + tig + 4]);
                af[mt][3] = __float_as_uint(As[rb_ + 8][ks + tig + 4]);
            }
            #pragma unroll
            for (int nt = 0; nt < 8; nt++) {
                const int nn = warp_n * 64 + nt * 8 + gid;
                bf[nt][0] = __float_as_uint(Bs[nn][ks + tig]);
                bf[nt][1] = __float_as_uint(Bs[nn][ks + tig + 4]);
            }
            #pragma unroll
            for (int mt = 0; mt < 2; mt++)
                #pragma unroll
                for (int nt = 0; nt < 8; nt++)
                    mma_tf32(acc[mt][nt], af[mt], bf[nt]);
        }
        __syncthreads();
        if (kc + 1 < NK) {
            #pragma unroll
            for (int i = 0; i < 4; i++) {
                int idx = i * 256 + tid, rr = idx >> 3, f = (idx & 7) * 4;
                *(float4*)&As[rr][f] = tf32x4(ra[i]);
                *(float4*)&Bs[rr][f] = tf32x4(rb[i]);
            }
            __syncthreads();
        }
    }
}

// ---------------- QKV projection (+bias, +RoPE) ------------------------------
__global__ __launch_bounds__(256) void qkv_mma(
    const float* __restrict__ x, const int* __restrict__ positions,
    const float* __restrict__ bq, const float* __restrict__ bk,
    const float* __restrict__ bv)
{
    __shared__ float As[128][PAD];
    __shared__ float Bs[128][PAD];

    const int tid  = threadIdx.x;
    const int lane = tid & 31;
    const int wid  = tid >> 5;
    const int warp_m = wid & 3, warp_n = wid >> 2;
    const int gid = lane >> 2, tig = lane & 3;
    const int m0 = blockIdx.y * 128, n0 = blockIdx.x * 128;

    const float* bias; float* outp; int ldout, nloc0, do_rope;
    if (n0 < QC)            { bias = bq; outp = g_Q; ldout = QC;  nloc0 = n0;            do_rope = 1; }
    else if (n0 < QC + KVC) { bias = bk; outp = g_K; ldout = KVC; nloc0 = n0 - QC;       do_rope = 1; }
    else                    { bias = bv; outp = g_V; ldout = KVC; nloc0 = n0 - QC - KVC; do_rope = 0; }

    float acc[2][8][4];
    #pragma unroll
    for (int a = 0; a < 2; a++)
        #pragma unroll
        for (int b = 0; b < 8; b++)
            #pragma unroll
            for (int d = 0; d < 4; d++) acc[a][b][d] = 0.f;

    gemm_mainloop(x, g_WT, m0, n0, HID, acc, As, Bs);

    #pragma unroll
    for (int mt = 0; mt < 2; mt++) {
        const int t_lo = m0 + warp_m * 32 + mt * 16 + gid;
        const int t_hi = t_lo + 8;
        float pos_lo = 0.f, pos_hi = 0.f;
        if (do_rope) { pos_lo = (float)positions[t_lo]; pos_hi = (float)positions[t_hi]; }
        #pragma unroll
        for (int nt = 0; nt < 8; nt++) {
            const int c = nloc0 + warp_n * 64 + nt * 8 + 2 * tig;
            const float b0 = bias[c], b1 = bias[c + 1];
            float v0 = acc[mt][nt][0] + b0, v1 = acc[mt][nt][1] + b1;
            float v2 = acc[mt][nt][2] + b0, v3 = acc[mt][nt][3] + b1;
            if (do_rope) {
                const int ip = (c & (DH - 1)) >> 1;
                const float inv_eff = 0.515625f * exp2f(-(float)ip * L2THETA_OVER_32);
                float s, co;
                __sincosf(pos_lo * (1.0f / 32.0f) * inv_eff, &s, &co);
                float e = v0 * co - v1 * s; v1 = v0 * s + v1 * co; v0 = e;
                __sincosf(pos_hi * (1.0f / 32.0f) * inv_eff, &s, &co);
                e = v2 * co - v3 * s; v3 = v2 * s + v3 * co; v2 = e;
            }
            *(float2*)(outp + (size_t)t_lo * ldout + c) = make_float2(v0, v1);
            *(float2*)(outp + (size_t)t_hi * ldout + c) = make_float2(v2, v3);
        }
    }
}

// ---------------- output projection (+bias) ----------------------------------
__global__ __launch_bounds__(256) void out_mma(
    const float* __restrict__ bo, float* __restrict__ out)
{
    __shared__ float As[128][PAD];
    __shared__ float Bs[128][PAD];

    const int tid  = threadIdx.x;
    const int lane = tid & 31;
    const int wid  = tid >> 5;
    const int warp_m = wid & 3, warp_n = wid >> 2;
    const int gid = lane >> 2, tig = lane & 3;
    const int m0 = blockIdx.y * 128, n0 = blockIdx.x * 128;

    float acc[2][8][4];
    #pragma unroll
    for (int a = 0; a < 2; a++)
        #pragma unroll
        for (int b = 0; b < 8; b++)
            #pragma unroll
            for (int d = 0; d < 4; d++) acc[a][b][d] = 0.f;

    gemm_mainloop(g_Y, g_WoT, m0, n0, QC, acc, As, Bs);

    #pragma unroll
    for (int mt = 0; mt < 2; mt++) {
        const int t_lo = m0 + warp_m * 32 + mt * 16 + gid;
        const int t_hi = t_lo + 8;
        #pragma unroll
        for (int nt = 0; nt < 8; nt++) {
            const int c = n0 + warp_n * 64 + nt * 8 + 2 * tig;
            if (c < NOUT) {
                const float b0 = bo[c], b1 = bo[c + 1];
                *(float2*)(out + (size_t)t_lo * NOUT + c) =
                    make_float2(acc[mt][nt][0] + b0, acc[mt][nt][1] + b1);
                *(float2*)(out + (size_t)t_hi * NOUT + c) =
                    make_float2(acc[mt][nt][2] + b0, acc[mt][nt][3] + b1);
            }
        }
    }
}

// ---------------- tensor-core flash attention (tf32 mma) ---------------------
// Block = (128 queries, 1 head). 8 warps x 16 query rows. Key chunks of 128.
// smem: Ks[128][68] (K, k-major), Vt[64][132] (V^T), Ps[128][132] (P tiles).
#define KS_STRIDE 68
#define VT_STRIDE 132
#define PS_STRIDE 132
#define OFF_VT (128*KS_STRIDE*4)                    /* 34816 */
#define OFF_PS (OFF_VT + 64*VT_STRIDE*4)            /* 68608 */
#define ATT_SMEM (OFF_PS + 128*PS_STRIDE*4)         /* 136192 */

__global__ __launch_bounds__(256) void attn_mma(
    const int* __restrict__ is_slide_p, const int* __restrict__ win_p)
{
    extern __shared__ char sm[];
    float (*Ks)[KS_STRIDE] = (float(*)[KS_STRIDE])(sm);
    float (*Vt)[VT_STRIDE] = (float(*)[VT_STRIDE])(sm + OFF_VT);
    float (*Ps)[PS_STRIDE] = (float(*)[PS_STRIDE])(sm + OFF_PS);

    const int tid = threadIdx.x, lane = tid & 31, wid = tid >> 5;
    const int gid = lane >> 2, tig = lane & 3;
    const int t0 = blockIdx.x * 128, h = blockIdx.y, kvh = h >> 3;
    const int is_slide = is_slide_p[0], W = win_p[0];

    const int r0 = t0 + wid * 16 + gid, r1 = r0 + 8;
    const int rlo0 = is_slide ? r0 - W : 0;
    const int rlo1 = is_slide ? r1 - W : 0;
    const int lrow = wid * 16 + gid;

    // Q fragments (registers, reused across chunks)
    uint32_t qf[8][4];
    {
        const float* q0 = g_Q + (size_t)r0 * QC + h * DH;
        const float* q1 = g_Q + (size_t)r1 * QC + h * DH;
        #pragma unroll
        for (int kk = 0; kk < 8; kk++) {
            qf[kk][0] = tf32_bits(q0[kk * 8 + tig]);
            qf[kk][1] = tf32_bits(q1[kk * 8 + tig]);
            qf[kk][2] = tf32_bits(q0[kk * 8 + tig + 4]);
            qf[kk][3] = tf32_bits(q1[kk * 8 + tig + 4]);
        }
    }

    float oc[8][4];
    #pragma unroll
    for (int nt = 0; nt < 8; nt++)
        #pragma unroll
        for (int d = 0; d < 4; d++) oc[nt][d] = 0.f;
    float m0v = -1e30f, m1v = -1e30f, l0 = 0.f, l1 = 0.f;

    const int cs0 = is_slide ? (max(0, t0 - W) & ~127) : 0;

    for (int cs = cs0; cs <= t0; cs += 128) {
        __syncthreads();
        // stage K chunk + V^T chunk (tf32-rounded)
        #pragma unroll
        for (int i = 0; i < 8; i++) {
            int idx = i * 256 + tid, rr = idx >> 4, c4 = (idx & 15) << 2;
            float4 kv = *(const float4*)(g_K + (size_t)(cs + rr) * KVC + kvh * DH + c4);
            *(float4*)&Ks[rr][c4] = tf32x4(kv);
            float4 vv = *(const float4*)(g_V + (size_t)(cs + rr) * KVC + kvh * DH + c4);
            vv = tf32x4(vv);
            Vt[c4 + 0][rr] = vv.x; Vt[c4 + 1][rr] = vv.y;
            Vt[c4 + 2][rr] = vv.z; Vt[c4 + 3][rr] = vv.w;
        }
        __syncthreads();

        // S = Q @ K^T  (16 n-tiles of 8 keys)
        float sc[16][4];
        #pragma unroll
        for (int nt = 0; nt < 16; nt++) {
            sc[nt][0] = sc[nt][1] = sc[nt][2] = sc[nt][3] = 0.f;
            #pragma unroll
            for (int kk = 0; kk < 8; kk++) {
                uint32_t bf[2];
                bf[0] = __float_as_uint(Ks[nt * 8 + gid][kk * 8 + tig]);
                bf[1] = __float_as_uint(Ks[nt * 8 + gid][kk * 8 + tig + 4]);
                mma_tf32(sc[nt], qf[kk], bf);
            }
        }

        // scale + mask
        float vmax0 = -1e30f, vmax1 = -1e30f;
        #pragma unroll
        for (int nt = 0; nt < 16; nt++) {
            const int s0 = cs + nt * 8 + 2 * tig, s1 = s0 + 1;
            float v0 = (s0 <= r0 && s0 >= rlo0) ? sc[nt][0] * 0.125f : -1e30f;
            float v1 = (s1 <= r0 && s1 >= rlo0) ? sc[nt][1] * 0.125f : -1e30f;
            float v2 = (s0 <= r1 && s0 >= rlo1) ? sc[nt][2] * 0.125f : -1e30f;
            float v3 = (s1 <= r1 && s1 >= rlo1) ? sc[nt][3] * 0.125f : -1e30f;
            sc[nt][0] = v0; sc[nt][1] = v1; sc[nt][2] = v2; sc[nt][3] = v3;
            vmax0 = fmaxf(vmax0, fmaxf(v0, v1));
            vmax1 = fmaxf(vmax1, fmaxf(v2, v3));
        }
        vmax0 = fmaxf(vmax0, __shfl_xor_sync(0xffffffffu, vmax0, 1));
        vmax0 = fmaxf(vmax0, __shfl_xor_sync(0xffffffffu, vmax0, 2));
        vmax1 = fmaxf(vmax1, __shfl_xor_sync(0xffffffffu, vmax1, 1));
        vmax1 = fmaxf(vmax1, __shfl_xor_sync(0xffffffffu, vmax1, 2));

        const float mn0 = fmaxf(m0v, vmax0), mn1 = fmaxf(m1v, vmax1);
        const float a0 = __expf(m0v - mn0), a1 = __expf(m1v - mn1);
        m0v = mn0; m1v = mn1;

        float ps0 = 0.f, ps1 = 0.f;
        #pragma unroll
        for (int nt = 0; nt < 16; nt++) {
            float p0 = __expf(sc[nt][0] - mn0), p1 = __expf(sc[nt][1] - mn0);
            float p2 = __expf(sc[nt][2] - mn1), p3 = __expf(sc[nt][3] - mn1);
            ps0 += p0 + p1; ps1 += p2 + p3;
            *(float2*)&Ps[lrow][nt * 8 + 2 * tig] =
                make_float2(__uint_as_float(tf32_bits(p0)), __uint_as_float(tf32_bits(p1)));
            *(float2*)&Ps[lrow + 8][nt * 8 + 2 * tig] =
                make_float2(__uint_as_float(tf32_bits(p2)), __uint_as_float(tf32_bits(p3)));
        }
        ps0 += __shfl_xor_sync(0xffffffffu, ps0, 1);
        ps0 += __shfl_xor_sync(0xffffffffu, ps0, 2);
        ps1 += __shfl_xor_sync(0xffffffffu, ps1, 1);
        ps1 += __shfl_xor_sync(0xffffffffu, ps1, 2);
        l0 = l0 * a0 + ps0;
        l1 = l1 * a1 + ps1;

        #pragma unroll
        for (int nt = 0; nt < 8; nt++) {
            oc[nt][0] *= a0; oc[nt][1] *= a0;
            oc[nt][2] *= a1; oc[nt][3] *= a1;
        }
        __syncwarp();

        // O += P @ V   (8 n-tiles of dims, 16 k-steps of keys)
        #pragma unroll
        for (int kk = 0; kk < 16; kk++) {
            uint32_t af[4];
            af[0] = __float_as_uint(Ps[lrow    ][kk * 8 + tig]);
            af[1] = __float_as_uint(Ps[lrow + 8][kk * 8 + tig]);
            af[2] = __float_as_uint(Ps[lrow    ][kk * 8 + tig + 4]);
            af[3] = __float_as_uint(Ps[lrow + 8][kk * 8 + tig + 4]);
            #pragma unroll
            for (int nt = 0; nt < 8; nt++) {
                uint32_t bf[2];
                bf[0] = __float_as_uint(Vt[nt * 8 + gid][kk * 8 + tig]);
                bf[1] = __float_as_uint(Vt[nt * 8 + gid][kk * 8 + tig + 4]);
                mma_tf32(oc[nt], af, bf);
            }
        }
    }

    const float i0 = 1.f / l0, i1 = 1.f / l1;
    #pragma unroll
    for (int nt = 0; nt < 8; nt++) {
        const int c = h * DH + nt * 8 + 2 * tig;
        *(float2*)(g_Y + (size_t)r0 * QC + c) = make_float2(oc[nt][0] * i0, oc[nt][1] * i0);
        *(float2*)(g_Y + (size_t)r1 * QC + c) = make_float2(oc[nt][2] * i1, oc[nt][3] * i1);
    }
}

// ---------------------------------------------------------------------------
extern "C" void kernel_launch(void* const* d_in, const int* in_sizes, int n_in,
                              void* d_out, int out_size)
{
    const float* x         = (const float*)d_in[0];
    const int*   positions = (const int*)  d_in[1];
    const float* Wq        = (const float*)d_in[2];
    const float* bq        = (const float*)d_in[3];
    const float* Wk        = (const float*)d_in[4];
    const float* bk        = (const float*)d_in[5];
    const float* Wv        = (const float*)d_in[6];
    const float* bv        = (const float*)d_in[7];
    const float* Wo        = (const float*)d_in[8];
    const float* bo        = (const float*)d_in[9];
    const int*   is_slide  = (const int*)  d_in[10];
    const int*   win       = (const int*)  d_in[11];

    cudaFuncSetAttribute(attn_mma, cudaFuncAttributeMaxDynamicSharedMemorySize, ATT_SMEM);

    dim3 tb(32, 8);
    transpose_qkv<<<dim3(NTOT / 32, HID / 32), tb>>>(Wq, Wk, Wv);
    transpose_wo <<<dim3(NOUT / 32, QC / 32),  tb>>>(Wo);

    qkv_mma<<<dim3(NTOT / 128, TSEQ / 128), 256>>>(x, positions, bq, bk, bv);

    attn_mma<<<dim3(TSEQ / 128, NHEAD), 256, ATT_SMEM>>>(is_slide, win);

    out_mma<<<dim3(NOUT_PAD / 128, TSEQ / 128), 256>>>(bo, (float*)d_out);
}

// round 5
// speedup vs baseline: 3.7064x; 1.0557x over previous
#include <cuda_runtime.h>
#include <math.h>
#include <stdint.h>

#define TSEQ 1536
#define HID  2880
#define NHEAD 64
#define NKVH  8
#define DH    64
#define QC   (NHEAD*DH)        /* 4096 */
#define KVC  (NKVH*DH)         /* 512  */
#define NTOT (QC + 2*KVC)      /* 5120 */
#define NOUT 2880
#define NOUT_PAD 2944          /* 23*128 */

#define L2THETA_OVER_32 0.53733134f

// ---------------- device-global scratch -------------------------------------
__device__ float g_Q[(size_t)TSEQ*QC];
__device__ float g_K[(size_t)TSEQ*KVC];
__device__ float g_V[(size_t)TSEQ*KVC];
__device__ float g_Y[(size_t)TSEQ*QC];     // attn out, tf32-rounded
__device__ float g_Xr[(size_t)TSEQ*HID];   // x, tf32-rounded
__device__ float g_WT[(size_t)NTOT*HID];   // qkv weights [n][k], tf32-rounded
__device__ float g_WoT[(size_t)NOUT_PAD*QC];// out weights [n][k], tf32-rounded (pad rows 0)

// ---------------- helpers ----------------------------------------------------
__device__ __forceinline__ uint32_t tf32_bits(float x) {
    uint32_t u;
    asm("cvt.rna.tf32.f32 %0, %1;" : "=r"(u) : "f"(x));
    return u;
}
__device__ __forceinline__ float tf32r(float x) { return __uint_as_float(tf32_bits(x)); }
__device__ __forceinline__ float4 tf32x4(float4 v) {
    v.x = tf32r(v.x); v.y = tf32r(v.y); v.z = tf32r(v.z); v.w = tf32r(v.w);
    return v;
}
__device__ __forceinline__ void mma_tf32(float c[4], const uint32_t a[4], const uint32_t b[2]) {
    asm volatile(
        "mma.sync.aligned.m16n8k8.row.col.f32.tf32.tf32.f32 "
        "{%0,%1,%2,%3}, {%4,%5,%6,%7}, {%8,%9}, {%0,%1,%2,%3};"
        : "+f"(c[0]), "+f"(c[1]), "+f"(c[2]), "+f"(c[3])
        : "r"(a[0]), "r"(a[1]), "r"(a[2]), "r"(a[3]), "r"(b[0]), "r"(b[1]));
}
__device__ __forceinline__ uint32_t smem_u32(const void* p) {
    uint32_t a;
    asm("{ .reg .u64 t; cvta.to.shared.u64 t, %1; cvt.u32.u64 %0, t; }" : "=r"(a) : "l"(p));
    return a;
}
__device__ __forceinline__ void cp16(uint32_t s, const void* g) {
    asm volatile("cp.async.cg.shared.global [%0], [%1], 16;" :: "r"(s), "l"(g));
}
#define CP_COMMIT() asm volatile("cp.async.commit_group;" ::: "memory")
#define CP_WAIT1()  asm volatile("cp.async.wait_group 1;" ::: "memory")

#define BK   32
#define PAD  36
#define STAGE_BYTES (2*128*PAD*4)       /* A+B per stage = 36864 */
#define GEMM_SMEM   (3*STAGE_BYTES)     /* 110592 */

// ---------------- prep kernels -----------------------------------------------
__global__ void round_x(const float* __restrict__ x)
{
    const size_t i = ((size_t)blockIdx.x * blockDim.x + threadIdx.x) * 4;
    if (i < (size_t)TSEQ * HID)
        *(float4*)(g_Xr + i) = tf32x4(*(const float4*)(x + i));
}

__global__ void transpose_qkv(const float* __restrict__ Wq,
                              const float* __restrict__ Wk,
                              const float* __restrict__ Wv)
{
    __shared__ float tile[32][33];
    const int n0 = blockIdx.x * 32, k0 = blockIdx.y * 32;
    const float* src; int ld, nb;
    if (n0 < QC)            { src = Wq; ld = QC;  nb = n0; }
    else if (n0 < QC + KVC) { src = Wk; ld = KVC; nb = n0 - QC; }
    else                    { src = Wv; ld = KVC; nb = n0 - QC - KVC; }
    const int tx = threadIdx.x, ty = threadIdx.y;
    #pragma unroll
    for (int i = 0; i < 32; i += 8)
        tile[ty + i][tx] = src[(size_t)(k0 + ty + i) * ld + nb + tx];
    __syncthreads();
    #pragma unroll
    for (int i = 0; i < 32; i += 8)
        g_WT[(size_t)(n0 + ty + i) * HID + k0 + tx] = tf32r(tile[tx][ty + i]);
}

__global__ void transpose_wo(const float* __restrict__ Wo)
{
    __shared__ float tile[32][33];
    const int n0 = blockIdx.x * 32, k0 = blockIdx.y * 32;
    const int tx = threadIdx.x, ty = threadIdx.y;
    #pragma unroll
    for (int i = 0; i < 32; i += 8)
        tile[ty + i][tx] = Wo[(size_t)(k0 + ty + i) * NOUT + n0 + tx];
    __syncthreads();
    #pragma unroll
    for (int i = 0; i < 32; i += 8)
        g_WoT[(size_t)(n0 + ty + i) * QC + k0 + tx] = tf32r(tile[tx][ty + i]);
}

// ---------------- GEMM mainloop: cp.async 3-stage, tf32 mma ------------------
// A, B already tf32-rounded in global. acc[2][8][4] per warp (32x64 warp tile).
__device__ __forceinline__ void gemm_mainloop_async(
    const float* __restrict__ Ag, const float* __restrict__ Bg,
    int m0, int n0, int K,
    float (&acc)[2][8][4], char* sm)
{
    const int tid  = threadIdx.x;
    const int lane = tid & 31;
    const int wid  = tid >> 5;
    const int warp_m = wid & 3, warp_n = wid >> 2;
    const int gid = lane >> 2, tig = lane & 3;
    const uint32_t sbase = smem_u32(sm);

    // loader mapping: thread covers 4 (row, f) pairs for A and B each
    int rr_[4], ff_[4];
    #pragma unroll
    for (int i = 0; i < 4; i++) {
        int idx = i * 256 + tid;
        rr_[i] = idx >> 3;
        ff_[i] = (idx & 7) * 4;
    }

    const int NK = K / BK;

    // issue stage s for k-chunk kc
    #define ISSUE(s, kc) do { \
        const uint32_t a_s = sbase + (s) * STAGE_BYTES; \
        const uint32_t b_s = a_s + 128 * PAD * 4; \
        const int kof = (kc) * BK; \
        _Pragma("unroll") \
        for (int i = 0; i < 4; i++) { \
            cp16(a_s + (rr_[i] * PAD + ff_[i]) * 4, Ag + (size_t)(m0 + rr_[i]) * K + kof + ff_[i]); \
            cp16(b_s + (rr_[i] * PAD + ff_[i]) * 4, Bg + (size_t)(n0 + rr_[i]) * K + kof + ff_[i]); \
        } \
        CP_COMMIT(); \
    } while (0)

    ISSUE(0, 0);
    ISSUE(1, 1);

    for (int kc = 0; kc < NK; kc++) {
        CP_WAIT1();
        __syncthreads();
        if (kc + 2 < NK) ISSUE((kc + 2) % 3, kc + 2);
        else             CP_COMMIT();          // keep group count uniform

        float (*As)[PAD] = (float(*)[PAD])(sm + (kc % 3) * STAGE_BYTES);
        float (*Bs)[PAD] = (float(*)[PAD])(sm + (kc % 3) * STAGE_BYTES + 128 * PAD * 4);

        #pragma unroll
        for (int ks = 0; ks < BK; ks += 8) {
            uint32_t af[2][4], bf[8][2];
            #pragma unroll
            for (int mt = 0; mt < 2; mt++) {
                const int rb_ = warp_m * 32 + mt * 16 + gid;
                af[mt][0] = __float_as_uint(As[rb_    ][ks + tig]);
                af[mt][1] = __float_as_uint(As[rb_ + 8][ks + tig]);
                af[mt][2] = __float_as_uint(As[rb_    ][ks + tig + 4]);
                af[mt][3] = __float_as_uint(As[rb_ + 8][ks + tig + 4]);
            }
            #pragma unroll
            for (int nt = 0; nt < 8; nt++) {
                const int nn = warp_n * 64 + nt * 8 + gid;
                bf[nt][0] = __float_as_uint(Bs[nn][ks + tig]);
                bf[nt][1] = __float_as_uint(Bs[nn][ks + tig + 4]);
            }
            #pragma unroll
            for (int mt = 0; mt < 2; mt++)
                #pragma unroll
                for (int nt = 0; nt < 8; nt++)
                    mma_tf32(acc[mt][nt], af[mt], bf[nt]);
        }
    }
    #undef ISSUE
}

// ---------------- QKV projection (+bias, +RoPE) ------------------------------
__global__ __launch_bounds__(256) void qkv_mma(
    const int* __restrict__ positions,
    const float* __restrict__ bq, const float* __restrict__ bk,
    const float* __restrict__ bv)
{
    extern __shared__ char sm[];
    const int tid  = threadIdx.x;
    const int lane = tid & 31;
    const int wid  = tid >> 5;
    const int warp_m = wid & 3, warp_n = wid >> 2;
    const int gid = lane >> 2, tig = lane & 3;
    const int m0 = blockIdx.y * 128, n0 = blockIdx.x * 128;

    const float* bias; float* outp; int ldout, nloc0, do_rope;
    if (n0 < QC)            { bias = bq; outp = g_Q; ldout = QC;  nloc0 = n0;            do_rope = 1; }
    else if (n0 < QC + KVC) { bias = bk; outp = g_K; ldout = KVC; nloc0 = n0 - QC;       do_rope = 1; }
    else                    { bias = bv; outp = g_V; ldout = KVC; nloc0 = n0 - QC - KVC; do_rope = 0; }

    float acc[2][8][4];
    #pragma unroll
    for (int a = 0; a < 2; a++)
        #pragma unroll
        for (int b = 0; b < 8; b++)
            #pragma unroll
            for (int d = 0; d < 4; d++) acc[a][b][d] = 0.f;

    gemm_mainloop_async(g_Xr, g_WT, m0, n0, HID, acc, sm);

    #pragma unroll
    for (int mt = 0; mt < 2; mt++) {
        const int t_lo = m0 + warp_m * 32 + mt * 16 + gid;
        const int t_hi = t_lo + 8;
        float pos_lo = 0.f, pos_hi = 0.f;
        if (do_rope) { pos_lo = (float)positions[t_lo]; pos_hi = (float)positions[t_hi]; }
        #pragma unroll
        for (int nt = 0; nt < 8; nt++) {
            const int c = nloc0 + warp_n * 64 + nt * 8 + 2 * tig;
            const float b0 = bias[c], b1 = bias[c + 1];
            float v0 = acc[mt][nt][0] + b0, v1 = acc[mt][nt][1] + b1;
            float v2 = acc[mt][nt][2] + b0, v3 = acc[mt][nt][3] + b1;
            if (do_rope) {
                const int ip = (c & (DH - 1)) >> 1;
                const float inv_eff = 0.515625f * exp2f(-(float)ip * L2THETA_OVER_32);
                float s, co;
                __sincosf(pos_lo * (1.0f / 32.0f) * inv_eff, &s, &co);
                float e = v0 * co - v1 * s; v1 = v0 * s + v1 * co; v0 = e;
                __sincosf(pos_hi * (1.0f / 32.0f) * inv_eff, &s, &co);
                e = v2 * co - v3 * s; v3 = v2 * s + v3 * co; v2 = e;
            }
            *(float2*)(outp + (size_t)t_lo * ldout + c) = make_float2(v0, v1);
            *(float2*)(outp + (size_t)t_hi * ldout + c) = make_float2(v2, v3);
        }
    }
}

// ---------------- output projection (+bias) ----------------------------------
__global__ __launch_bounds__(256) void out_mma(
    const float* __restrict__ bo, float* __restrict__ out)
{
    extern __shared__ char sm[];
    const int tid  = threadIdx.x;
    const int lane = tid & 31;
    const int wid  = tid >> 5;
    const int warp_m = wid & 3, warp_n = wid >> 2;
    const int gid = lane >> 2, tig = lane & 3;
    const int m0 = blockIdx.y * 128, n0 = blockIdx.x * 128;

    float acc[2][8][4];
    #pragma unroll
    for (int a = 0; a < 2; a++)
        #pragma unroll
        for (int b = 0; b < 8; b++)
            #pragma unroll
            for (int d = 0; d < 4; d++) acc[a][b][d] = 0.f;

    gemm_mainloop_async(g_Y, g_WoT, m0, n0, QC, acc, sm);

    #pragma unroll
    for (int mt = 0; mt < 2; mt++) {
        const int t_lo = m0 + warp_m * 32 + mt * 16 + gid;
        const int t_hi = t_lo + 8;
        #pragma unroll
        for (int nt = 0; nt < 8; nt++) {
            const int c = n0 + warp_n * 64 + nt * 8 + 2 * tig;
            if (c < NOUT) {
                const float b0 = bo[c], b1 = bo[c + 1];
                *(float2*)(out + (size_t)t_lo * NOUT + c) =
                    make_float2(acc[mt][nt][0] + b0, acc[mt][nt][1] + b1);
                *(float2*)(out + (size_t)t_hi * NOUT + c) =
                    make_float2(acc[mt][nt][2] + b0, acc[mt][nt][3] + b1);
            }
        }
    }
}

// ---------------- tensor-core flash attention (tf32 mma) ---------------------
#define KS_STRIDE 68
#define VT_STRIDE 132
#define PS_STRIDE 132
#define OFF_VT (128*KS_STRIDE*4)
#define OFF_PS (OFF_VT + 64*VT_STRIDE*4)
#define ATT_SMEM (OFF_PS + 128*PS_STRIDE*4)

__global__ __launch_bounds__(256) void attn_mma(
    const int* __restrict__ is_slide_p, const int* __restrict__ win_p)
{
    extern __shared__ char sm[];
    float (*Ks)[KS_STRIDE] = (float(*)[KS_STRIDE])(sm);
    float (*Vt)[VT_STRIDE] = (float(*)[VT_STRIDE])(sm + OFF_VT);
    float (*Ps)[PS_STRIDE] = (float(*)[PS_STRIDE])(sm + OFF_PS);

    const int tid = threadIdx.x, lane = tid & 31, wid = tid >> 5;
    const int gid = lane >> 2, tig = lane & 3;
    const int t0 = blockIdx.x * 128, h = blockIdx.y, kvh = h >> 3;
    const int is_slide = is_slide_p[0], W = win_p[0];

    const int r0 = t0 + wid * 16 + gid, r1 = r0 + 8;
    const int rlo0 = is_slide ? r0 - W : 0;
    const int rlo1 = is_slide ? r1 - W : 0;
    const int lrow = wid * 16 + gid;

    uint32_t qf[8][4];
    {
        const float* q0 = g_Q + (size_t)r0 * QC + h * DH;
        const float* q1 = g_Q + (size_t)r1 * QC + h * DH;
        #pragma unroll
        for (int kk = 0; kk < 8; kk++) {
            qf[kk][0] = tf32_bits(q0[kk * 8 + tig]);
            qf[kk][1] = tf32_bits(q1[kk * 8 + tig]);
            qf[kk][2] = tf32_bits(q0[kk * 8 + tig + 4]);
            qf[kk][3] = tf32_bits(q1[kk * 8 + tig + 4]);
        }
    }

    float oc[8][4];
    #pragma unroll
    for (int nt = 0; nt < 8; nt++)
        #pragma unroll
        for (int d = 0; d < 4; d++) oc[nt][d] = 0.f;
    float m0v = -1e30f, m1v = -1e30f, l0 = 0.f, l1 = 0.f;

    const int cs0 = is_slide ? (max(0, t0 - W) & ~127) : 0;

    for (int cs = cs0; cs <= t0; cs += 128) {
        __syncthreads();
        #pragma unroll
        for (int i = 0; i < 8; i++) {
            int idx = i * 256 + tid, rr = idx >> 4, c4 = (idx & 15) << 2;
            float4 kv = *(const float4*)(g_K + (size_t)(cs + rr) * KVC + kvh * DH + c4);
            *(float4*)&Ks[rr][c4] = tf32x4(kv);
            float4 vv = *(const float4*)(g_V + (size_t)(cs + rr) * KVC + kvh * DH + c4);
            vv = tf32x4(vv);
            Vt[c4 + 0][rr] = vv.x; Vt[c4 + 1][rr] = vv.y;
            Vt[c4 + 2][rr] = vv.z; Vt[c4 + 3][rr] = vv.w;
        }
        __syncthreads();

        float sc[16][4];
        #pragma unroll
        for (int nt = 0; nt < 16; nt++) {
            sc[nt][0] = sc[nt][1] = sc[nt][2] = sc[nt][3] = 0.f;
            #pragma unroll
            for (int kk = 0; kk < 8; kk++) {
                uint32_t bf[2];
                bf[0] = __float_as_uint(Ks[nt * 8 + gid][kk * 8 + tig]);
                bf[1] = __float_as_uint(Ks[nt * 8 + gid][kk * 8 + tig + 4]);
                mma_tf32(sc[nt], qf[kk], bf);
            }
        }

        float vmax0 = -1e30f, vmax1 = -1e30f;
        #pragma unroll
        for (int nt = 0; nt < 16; nt++) {
            const int s0 = cs + nt * 8 + 2 * tig, s1 = s0 + 1;
            float v0 = (s0 <= r0 && s0 >= rlo0) ? sc[nt][0] * 0.125f : -1e30f;
            float v1 = (s1 <= r0 && s1 >= rlo0) ? sc[nt][1] * 0.125f : -1e30f;
            float v2 = (s0 <= r1 && s0 >= rlo1) ? sc[nt][2] * 0.125f : -1e30f;
            float v3 = (s1 <= r1 && s1 >= rlo1) ? sc[nt][3] * 0.125f : -1e30f;
            sc[nt][0] = v0; sc[nt][1] = v1; sc[nt][2] = v2; sc[nt][3] = v3;
            vmax0 = fmaxf(vmax0, fmaxf(v0, v1));
            vmax1 = fmaxf(vmax1, fmaxf(v2, v3));
        }
        vmax0 = fmaxf(vmax0, __shfl_xor_sync(0xffffffffu, vmax0, 1));
        vmax0 = fmaxf(vmax0, __shfl_xor_sync(0xffffffffu, vmax0, 2));
        vmax1 = fmaxf(vmax1, __shfl_xor_sync(0xffffffffu, vmax1, 1));
        vmax1 = fmaxf(vmax1, __shfl_xor_sync(0xffffffffu, vmax1, 2));

        const float mn0 = fmaxf(m0v, vmax0), mn1 = fmaxf(m1v, vmax1);
        const float a0 = __expf(m0v - mn0), a1 = __expf(m1v - mn1);
        m0v = mn0; m1v = mn1;

        float ps0 = 0.f, ps1 = 0.f;
        #pragma unroll
        for (int nt = 0; nt < 16; nt++) {
            float p0 = __expf(sc[nt][0] - mn0), p1 = __expf(sc[nt][1] - mn0);
            float p2 = __expf(sc[nt][2] - mn1), p3 = __expf(sc[nt][3] - mn1);
            ps0 += p0 + p1; ps1 += p2 + p3;
            *(float2*)&Ps[lrow][nt * 8 + 2 * tig] = make_float2(tf32r(p0), tf32r(p1));
            *(float2*)&Ps[lrow + 8][nt * 8 + 2 * tig] = make_float2(tf32r(p2), tf32r(p3));
        }
        ps0 += __shfl_xor_sync(0xffffffffu, ps0, 1);
        ps0 += __shfl_xor_sync(0xffffffffu, ps0, 2);
        ps1 += __shfl_xor_sync(0xffffffffu, ps1, 1);
        ps1 += __shfl_xor_sync(0xffffffffu, ps1, 2);
        l0 = l0 * a0 + ps0;
        l1 = l1 * a1 + ps1;

        #pragma unroll
        for (int nt = 0; nt < 8; nt++) {
            oc[nt][0] *= a0; oc[nt][1] *= a0;
            oc[nt][2] *= a1; oc[nt][3] *= a1;
        }
        __syncwarp();

        #pragma unroll
        for (int kk = 0; kk < 16; kk++) {
            uint32_t af[4];
            af[0] = __float_as_uint(Ps[lrow    ][kk * 8 + tig]);
            af[1] = __float_as_uint(Ps[lrow + 8][kk * 8 + tig]);
            af[2] = __float_as_uint(Ps[lrow    ][kk * 8 + tig + 4]);
            af[3] = __float_as_uint(Ps[lrow + 8][kk * 8 + tig + 4]);
            #pragma unroll
            for (int nt = 0; nt < 8; nt++) {
                uint32_t bf[2];
                bf[0] = __float_as_uint(Vt[nt * 8 + gid][kk * 8 + tig]);
                bf[1] = __float_as_uint(Vt[nt * 8 + gid][kk * 8 + tig + 4]);
                mma_tf32(oc[nt], af, bf);
            }
        }
    }

    // write g_Y tf32-rounded (consumed by out_mma without further conversion)
    const float i0 = 1.f / l0, i1 = 1.f / l1;
    #pragma unroll
    for (int nt = 0; nt < 8; nt++) {
        const int c = h * DH + nt * 8 + 2 * tig;
        *(float2*)(g_Y + (size_t)r0 * QC + c) =
            make_float2(tf32r(oc[nt][0] * i0), tf32r(oc[nt][1] * i0));
        *(float2*)(g_Y + (size_t)r1 * QC + c) =
            make_float2(tf32r(oc[nt][2] * i1), tf32r(oc[nt][3] * i1));
    }
}

// ---------------------------------------------------------------------------
extern "C" void kernel_launch(void* const* d_in, const int* in_sizes, int n_in,
                              void* d_out, int out_size)
{
    const float* x         = (const float*)d_in[0];
    const int*   positions = (const int*)  d_in[1];
    const float* Wq        = (const float*)d_in[2];
    const float* bq        = (const float*)d_in[3];
    const float* Wk        = (const float*)d_in[4];
    const float* bk        = (const float*)d_in[5];
    const float* Wv        = (const float*)d_in[6];
    const float* bv        = (const float*)d_in[7];
    const float* Wo        = (const float*)d_in[8];
    const float* bo        = (const float*)d_in[9];
    const int*   is_slide  = (const int*)  d_in[10];
    const int*   win       = (const int*)  d_in[11];

    cudaFuncSetAttribute(attn_mma, cudaFuncAttributeMaxDynamicSharedMemorySize, ATT_SMEM);
    cudaFuncSetAttribute(qkv_mma,  cudaFuncAttributeMaxDynamicSharedMemorySize, GEMM_SMEM);
    cudaFuncSetAttribute(out_mma,  cudaFuncAttributeMaxDynamicSharedMemorySize, GEMM_SMEM);

    dim3 tb(32, 8);
    round_x<<<(TSEQ * HID / 4 + 255) / 256, 256>>>(x);
    transpose_qkv<<<dim3(NTOT / 32, HID / 32), tb>>>(Wq, Wk, Wv);
    transpose_wo <<<dim3(NOUT / 32, QC / 32),  tb>>>(Wo);

    qkv_mma<<<dim3(NTOT / 128, TSEQ / 128), 256, GEMM_SMEM>>>(positions, bq, bk, bv);

    attn_mma<<<dim3(TSEQ / 128, NHEAD), 256, ATT_SMEM>>>(is_slide, win);

    out_mma<<<dim3(NOUT_PAD / 128, TSEQ / 128), 256, GEMM_SMEM>>>(bo, (float*)d_out);
}

// round 6
// speedup vs baseline: 5.8588x; 1.5807x over previous
#include <cuda_runtime.h>
#include <cuda_fp16.h>
#include <math.h>
#include <stdint.h>

#define TSEQ 1536
#define HID  2880
#define NHEAD 64
#define NKVH  8
#define DH    64
#define QC   (NHEAD*DH)        /* 4096 */
#define KVC  (NKVH*DH)         /* 512  */
#define NTOT (QC + 2*KVC)      /* 5120 */
#define NOUT 2880
#define NOUT_PAD 2944          /* 23*128 */

#define L2THETA_OVER_32 0.53733134f

// ---------------- device-global scratch (zero-initialized) -------------------
__device__ __half g_Xh[(size_t)TSEQ*HID];
__device__ __half g_WTh[(size_t)NTOT*HID];     // qkv weights [n][k]
__device__ __half g_WoTh[(size_t)NOUT_PAD*QC]; // out weights [n][k], pad rows stay 0
__device__ __half g_Qh[(size_t)TSEQ*QC];
__device__ __half g_Kh[(size_t)TSEQ*KVC];
__device__ __half g_Vh[(size_t)TSEQ*KVC];
__device__ __half g_Yh[(size_t)TSEQ*QC];

// ---------------- helpers ----------------------------------------------------
__device__ __forceinline__ void mma_f16(float c[4], const uint32_t a[4], const uint32_t b[2]) {
    asm volatile(
        "mma.sync.aligned.m16n8k16.row.col.f32.f16.f16.f32 "
        "{%0,%1,%2,%3}, {%4,%5,%6,%7}, {%8,%9}, {%0,%1,%2,%3};"
        : "+f"(c[0]), "+f"(c[1]), "+f"(c[2]), "+f"(c[3])
        : "r"(a[0]), "r"(a[1]), "r"(a[2]), "r"(a[3]), "r"(b[0]), "r"(b[1]));
}
__device__ __forceinline__ uint32_t smem_u32(const void* p) {
    uint32_t a;
    asm("{ .reg .u64 t; cvta.to.shared.u64 t, %1; cvt.u32.u64 %0, t; }" : "=r"(a) : "l"(p));
    return a;
}
__device__ __forceinline__ void cp16(uint32_t s, const void* g) {
    asm volatile("cp.async.cg.shared.global [%0], [%1], 16;" :: "r"(s), "l"(g));
}
#define CP_COMMIT() asm volatile("cp.async.commit_group;" ::: "memory")
#define CP_WAIT1()  asm volatile("cp.async.wait_group 1;" ::: "memory")

#define BK     32                      /* halves per k-chunk */
#define PAD_H  40                      /* halves per smem row (32 data + 8 pad) */
#define STAGE_BYTES (2*128*PAD_H*2)    /* A+B per stage = 20480 */
#define GEMM_SMEM   (3*STAGE_BYTES)    /* 61440 */

// ---------------- prep kernels -----------------------------------------------
__global__ void conv_x(const float* __restrict__ x)
{
    const size_t i = ((size_t)blockIdx.x * blockDim.x + threadIdx.x) * 4;
    if (i < (size_t)TSEQ * HID) {
        float4 v = *(const float4*)(x + i);
        __half2 h0 = __floats2half2_rn(v.x, v.y);
        __half2 h1 = __floats2half2_rn(v.z, v.w);
        *(uint2*)(g_Xh + i) = make_uint2(*(uint32_t*)&h0, *(uint32_t*)&h1);
    }
}

__global__ void transpose_qkv(const float* __restrict__ Wq,
                              const float* __restrict__ Wk,
                              const float* __restrict__ Wv)
{
    __shared__ float tile[32][33];
    const int n0 = blockIdx.x * 32, k0 = blockIdx.y * 32;
    const float* src; int ld, nb;
    if (n0 < QC)            { src = Wq; ld = QC;  nb = n0; }
    else if (n0 < QC + KVC) { src = Wk; ld = KVC; nb = n0 - QC; }
    else                    { src = Wv; ld = KVC; nb = n0 - QC - KVC; }
    const int tx = threadIdx.x, ty = threadIdx.y;
    #pragma unroll
    for (int i = 0; i < 32; i += 8)
        tile[ty + i][tx] = src[(size_t)(k0 + ty + i) * ld + nb + tx];
    __syncthreads();
    #pragma unroll
    for (int i = 0; i < 32; i += 8)
        g_WTh[(size_t)(n0 + ty + i) * HID + k0 + tx] = __float2half_rn(tile[tx][ty + i]);
}

__global__ void transpose_wo(const float* __restrict__ Wo)
{
    __shared__ float tile[32][33];
    const int n0 = blockIdx.x * 32, k0 = blockIdx.y * 32;
    const int tx = threadIdx.x, ty = threadIdx.y;
    #pragma unroll
    for (int i = 0; i < 32; i += 8)
        tile[ty + i][tx] = Wo[(size_t)(k0 + ty + i) * NOUT + n0 + tx];
    __syncthreads();
    #pragma unroll
    for (int i = 0; i < 32; i += 8)
        g_WoTh[(size_t)(n0 + ty + i) * QC + k0 + tx] = __float2half_rn(tile[tx][ty + i]);
}

// ---------------- GEMM mainloop: cp.async 3-stage, fp16 m16n8k16 -------------
__device__ __forceinline__ void gemm_mainloop_f16(
    const __half* __restrict__ Ag, const __half* __restrict__ Bg,
    int m0, int n0, int K,
    float (&acc)[2][8][4], char* sm)
{
    const int tid  = threadIdx.x;
    const int lane = tid & 31;
    const int wid  = tid >> 5;
    const int warp_m = wid & 3, warp_n = wid >> 2;
    const int gid = lane >> 2, tig = lane & 3;
    const uint32_t sbase = smem_u32(sm);

    // loader: 128 rows x 4 chunks(8 halves) per matrix; 256 thr -> 2 each
    int rr_[2], ff_[2];
    #pragma unroll
    for (int i = 0; i < 2; i++) {
        int idx = i * 256 + tid;
        rr_[i] = idx >> 2;
        ff_[i] = (idx & 3) * 8;
    }

    const int NK = K / BK;

    #define ISSUE(s, kc) do { \
        const uint32_t a_s = sbase + (s) * STAGE_BYTES; \
        const uint32_t b_s = a_s + 128 * PAD_H * 2; \
        const int kof = (kc) * BK; \
        _Pragma("unroll") \
        for (int i = 0; i < 2; i++) { \
            cp16(a_s + (rr_[i] * PAD_H + ff_[i]) * 2, Ag + (size_t)(m0 + rr_[i]) * K + kof + ff_[i]); \
            cp16(b_s + (rr_[i] * PAD_H + ff_[i]) * 2, Bg + (size_t)(n0 + rr_[i]) * K + kof + ff_[i]); \
        } \
        CP_COMMIT(); \
    } while (0)

    ISSUE(0, 0);
    ISSUE(1, 1);

    for (int kc = 0; kc < NK; kc++) {
        CP_WAIT1();
        __syncthreads();
        if (kc + 2 < NK) ISSUE((kc + 2) % 3, kc + 2);
        else             CP_COMMIT();

        __half (*As)[PAD_H] = (__half(*)[PAD_H])(sm + (kc % 3) * STAGE_BYTES);
        __half (*Bs)[PAD_H] = (__half(*)[PAD_H])(sm + (kc % 3) * STAGE_BYTES + 128 * PAD_H * 2);

        #pragma unroll
        for (int ks = 0; ks < BK; ks += 16) {
            uint32_t af[2][4], bf[8][2];
            #pragma unroll
            for (int mt = 0; mt < 2; mt++) {
                const int rb_ = warp_m * 32 + mt * 16 + gid;
                af[mt][0] = *(const uint32_t*)&As[rb_    ][ks + 2 * tig];
                af[mt][1] = *(const uint32_t*)&As[rb_ + 8][ks + 2 * tig];
                af[mt][2] = *(const uint32_t*)&As[rb_    ][ks + 2 * tig + 8];
                af[mt][3] = *(const uint32_t*)&As[rb_ + 8][ks + 2 * tig + 8];
            }
            #pragma unroll
            for (int nt = 0; nt < 8; nt++) {
                const int nn = warp_n * 64 + nt * 8 + gid;
                bf[nt][0] = *(const uint32_t*)&Bs[nn][ks + 2 * tig];
                bf[nt][1] = *(const uint32_t*)&Bs[nn][ks + 2 * tig + 8];
            }
            #pragma unroll
            for (int mt = 0; mt < 2; mt++)
                #pragma unroll
                for (int nt = 0; nt < 8; nt++)
                    mma_f16(acc[mt][nt], af[mt], bf[nt]);
        }
    }
    #undef ISSUE
}

// ---------------- QKV projection (+bias, +RoPE) ------------------------------
__global__ __launch_bounds__(256) void qkv_mma(
    const int* __restrict__ positions,
    const float* __restrict__ bq, const float* __restrict__ bk,
    const float* __restrict__ bv)
{
    extern __shared__ char sm[];
    const int tid  = threadIdx.x;
    const int lane = tid & 31;
    const int wid  = tid >> 5;
    const int warp_m = wid & 3, warp_n = wid >> 2;
    const int gid = lane >> 2, tig = lane & 3;
    const int m0 = blockIdx.y * 128, n0 = blockIdx.x * 128;

    const float* bias; __half* outp; int ldout, nloc0, do_rope;
    if (n0 < QC)            { bias = bq; outp = g_Qh; ldout = QC;  nloc0 = n0;            do_rope = 1; }
    else if (n0 < QC + KVC) { bias = bk; outp = g_Kh; ldout = KVC; nloc0 = n0 - QC;       do_rope = 1; }
    else                    { bias = bv; outp = g_Vh; ldout = KVC; nloc0 = n0 - QC - KVC; do_rope = 0; }

    float acc[2][8][4];
    #pragma unroll
    for (int a = 0; a < 2; a++)
        #pragma unroll
        for (int b = 0; b < 8; b++)
            #pragma unroll
            for (int d = 0; d < 4; d++) acc[a][b][d] = 0.f;

    gemm_mainloop_f16(g_Xh, g_WTh, m0, n0, HID, acc, sm);

    #pragma unroll
    for (int mt = 0; mt < 2; mt++) {
        const int t_lo = m0 + warp_m * 32 + mt * 16 + gid;
        const int t_hi = t_lo + 8;
        float pos_lo = 0.f, pos_hi = 0.f;
        if (do_rope) { pos_lo = (float)positions[t_lo]; pos_hi = (float)positions[t_hi]; }
        #pragma unroll
        for (int nt = 0; nt < 8; nt++) {
            const int c = nloc0 + warp_n * 64 + nt * 8 + 2 * tig;
            const float b0 = bias[c], b1 = bias[c + 1];
            float v0 = acc[mt][nt][0] + b0, v1 = acc[mt][nt][1] + b1;
            float v2 = acc[mt][nt][2] + b0, v3 = acc[mt][nt][3] + b1;
            if (do_rope) {
                const int ip = (c & (DH - 1)) >> 1;
                const float inv_eff = 0.515625f * exp2f(-(float)ip * L2THETA_OVER_32);
                float s, co;
                __sincosf(pos_lo * (1.0f / 32.0f) * inv_eff, &s, &co);
                float e = v0 * co - v1 * s; v1 = v0 * s + v1 * co; v0 = e;
                __sincosf(pos_hi * (1.0f / 32.0f) * inv_eff, &s, &co);
                e = v2 * co - v3 * s; v3 = v2 * s + v3 * co; v2 = e;
            }
            *(__half2*)(outp + (size_t)t_lo * ldout + c) = __floats2half2_rn(v0, v1);
            *(__half2*)(outp + (size_t)t_hi * ldout + c) = __floats2half2_rn(v2, v3);
        }
    }
}

// ---------------- output projection (+bias) ----------------------------------
__global__ __launch_bounds__(256) void out_mma(
    const float* __restrict__ bo, float* __restrict__ out)
{
    extern __shared__ char sm[];
    const int tid  = threadIdx.x;
    const int lane = tid & 31;
    const int wid  = tid >> 5;
    const int warp_m = wid & 3, warp_n = wid >> 2;
    const int gid = lane >> 2, tig = lane & 3;
    const int m0 = blockIdx.y * 128, n0 = blockIdx.x * 128;

    float acc[2][8][4];
    #pragma unroll
    for (int a = 0; a < 2; a++)
        #pragma unroll
        for (int b = 0; b < 8; b++)
            #pragma unroll
            for (int d = 0; d < 4; d++) acc[a][b][d] = 0.f;

    gemm_mainloop_f16(g_Yh, g_WoTh, m0, n0, QC, acc, sm);

    #pragma unroll
    for (int mt = 0; mt < 2; mt++) {
        const int t_lo = m0 + warp_m * 32 + mt * 16 + gid;
        const int t_hi = t_lo + 8;
        #pragma unroll
        for (int nt = 0; nt < 8; nt++) {
            const int c = n0 + warp_n * 64 + nt * 8 + 2 * tig;
            if (c < NOUT) {
                const float b0 = bo[c], b1 = bo[c + 1];
                *(float2*)(out + (size_t)t_lo * NOUT + c) =
                    make_float2(acc[mt][nt][0] + b0, acc[mt][nt][1] + b1);
                *(float2*)(out + (size_t)t_hi * NOUT + c) =
                    make_float2(acc[mt][nt][2] + b0, acc[mt][nt][3] + b1);
            }
        }
    }
}

// ---------------- tensor-core flash attention (fp16 mma) ---------------------
#define KS_H 72    /* halves per Ks row  (64 data + 8 pad)  */
#define VT_H 136   /* halves per Vt row  (128 data + 8 pad) */
#define PS_H 136   /* halves per Ps row  (128 data + 8 pad) */
#define OFF_VT (128*KS_H*2)
#define OFF_PS (OFF_VT + 64*VT_H*2)
#define ATT_SMEM (OFF_PS + 128*PS_H*2)   /* 70656 */

__global__ __launch_bounds__(256) void attn_mma(
    const int* __restrict__ is_slide_p, const int* __restrict__ win_p)
{
    extern __shared__ char sm[];
    __half (*Ks)[KS_H] = (__half(*)[KS_H])(sm);
    __half (*Vt)[VT_H] = (__half(*)[VT_H])(sm + OFF_VT);
    __half (*Ps)[PS_H] = (__half(*)[PS_H])(sm + OFF_PS);

    const int tid = threadIdx.x, lane = tid & 31, wid = tid >> 5;
    const int gid = lane >> 2, tig = lane & 3;
    const int t0 = blockIdx.x * 128, h = blockIdx.y, kvh = h >> 3;
    const int is_slide = is_slide_p[0], W = win_p[0];

    const int r0 = t0 + wid * 16 + gid, r1 = r0 + 8;
    const int rlo0 = is_slide ? r0 - W : 0;
    const int rlo1 = is_slide ? r1 - W : 0;
    const int lrow = wid * 16 + gid;

    // Q fragments (4 k16 steps over DH=64)
    uint32_t qf[4][4];
    {
        const __half* q0 = g_Qh + (size_t)r0 * QC + h * DH;
        const __half* q1 = g_Qh + (size_t)r1 * QC + h * DH;
        #pragma unroll
        for (int kk = 0; kk < 4; kk++) {
            qf[kk][0] = *(const uint32_t*)(q0 + kk * 16 + 2 * tig);
            qf[kk][1] = *(const uint32_t*)(q1 + kk * 16 + 2 * tig);
            qf[kk][2] = *(const uint32_t*)(q0 + kk * 16 + 2 * tig + 8);
            qf[kk][3] = *(const uint32_t*)(q1 + kk * 16 + 2 * tig + 8);
        }
    }

    float oc[8][4];
    #pragma unroll
    for (int nt = 0; nt < 8; nt++)
        #pragma unroll
        for (int d = 0; d < 4; d++) oc[nt][d] = 0.f;
    float m0v = -1e30f, m1v = -1e30f, l0 = 0.f, l1 = 0.f;

    const int cs0 = is_slide ? (max(0, t0 - W) & ~127) : 0;

    for (int cs = cs0; cs <= t0; cs += 128) {
        __syncthreads();
        // stage K chunk (row-major) and V chunk (transposed)
        #pragma unroll
        for (int i = 0; i < 4; i++) {
            int idx = i * 256 + tid, rr = idx >> 3, c8 = (idx & 7) * 8;
            *(uint4*)&Ks[rr][c8] =
                *(const uint4*)(g_Kh + (size_t)(cs + rr) * KVC + kvh * DH + c8);
            union { uint4 u; __half hv[8]; } v;
            v.u = *(const uint4*)(g_Vh + (size_t)(cs + rr) * KVC + kvh * DH + c8);
            #pragma unroll
            for (int j = 0; j < 8; j++) Vt[c8 + j][rr] = v.hv[j];
        }
        __syncthreads();

        // S = Q @ K^T  (16 n-tiles x 4 k-steps)
        float sc[16][4];
        #pragma unroll
        for (int nt = 0; nt < 16; nt++) {
            sc[nt][0] = sc[nt][1] = sc[nt][2] = sc[nt][3] = 0.f;
            #pragma unroll
            for (int kk = 0; kk < 4; kk++) {
                uint32_t bf[2];
                bf[0] = *(const uint32_t*)&Ks[nt * 8 + gid][kk * 16 + 2 * tig];
                bf[1] = *(const uint32_t*)&Ks[nt * 8 + gid][kk * 16 + 2 * tig + 8];
                mma_f16(sc[nt], qf[kk], bf);
            }
        }

        // scale + mask + online softmax
        float vmax0 = -1e30f, vmax1 = -1e30f;
        #pragma unroll
        for (int nt = 0; nt < 16; nt++) {
            const int s0 = cs + nt * 8 + 2 * tig, s1 = s0 + 1;
            float v0 = (s0 <= r0 && s0 >= rlo0) ? sc[nt][0] * 0.125f : -1e30f;
            float v1 = (s1 <= r0 && s1 >= rlo0) ? sc[nt][1] * 0.125f : -1e30f;
            float v2 = (s0 <= r1 && s0 >= rlo1) ? sc[nt][2] * 0.125f : -1e30f;
            float v3 = (s1 <= r1 && s1 >= rlo1) ? sc[nt][3] * 0.125f : -1e30f;
            sc[nt][0] = v0; sc[nt][1] = v1; sc[nt][2] = v2; sc[nt][3] = v3;
            vmax0 = fmaxf(vmax0, fmaxf(v0, v1));
            vmax1 = fmaxf(vmax1, fmaxf(v2, v3));
        }
        vmax0 = fmaxf(vmax0, __shfl_xor_sync(0xffffffffu, vmax0, 1));
        vmax0 = fmaxf(vmax0, __shfl_xor_sync(0xffffffffu, vmax0, 2));
        vmax1 = fmaxf(vmax1, __shfl_xor_sync(0xffffffffu, vmax1, 1));
        vmax1 = fmaxf(vmax1, __shfl_xor_sync(0xffffffffu, vmax1, 2));

        const float mn0 = fmaxf(m0v, vmax0), mn1 = fmaxf(m1v, vmax1);
        const float a0 = __expf(m0v - mn0), a1 = __expf(m1v - mn1);
        m0v = mn0; m1v = mn1;

        float ps0 = 0.f, ps1 = 0.f;
        #pragma unroll
        for (int nt = 0; nt < 16; nt++) {
            float p0 = __expf(sc[nt][0] - mn0), p1 = __expf(sc[nt][1] - mn0);
            float p2 = __expf(sc[nt][2] - mn1), p3 = __expf(sc[nt][3] - mn1);
            ps0 += p0 + p1; ps1 += p2 + p3;
            *(__half2*)&Ps[lrow][nt * 8 + 2 * tig] = __floats2half2_rn(p0, p1);
            *(__half2*)&Ps[lrow + 8][nt * 8 + 2 * tig] = __floats2half2_rn(p2, p3);
        }
        ps0 += __shfl_xor_sync(0xffffffffu, ps0, 1);
        ps0 += __shfl_xor_sync(0xffffffffu, ps0, 2);
        ps1 += __shfl_xor_sync(0xffffffffu, ps1, 1);
        ps1 += __shfl_xor_sync(0xffffffffu, ps1, 2);
        l0 = l0 * a0 + ps0;
        l1 = l1 * a1 + ps1;

        #pragma unroll
        for (int nt = 0; nt < 8; nt++) {
            oc[nt][0] *= a0; oc[nt][1] *= a0;
            oc[nt][2] *= a1; oc[nt][3] *= a1;
        }
        __syncwarp();

        // O += P @ V  (8 dim-tiles x 8 k16 steps over 128 keys)
        #pragma unroll
        for (int kk = 0; kk < 8; kk++) {
            uint32_t af[4];
            af[0] = *(const uint32_t*)&Ps[lrow    ][kk * 16 + 2 * tig];
            af[1] = *(const uint32_t*)&Ps[lrow + 8][kk * 16 + 2 * tig];
            af[2] = *(const uint32_t*)&Ps[lrow    ][kk * 16 + 2 * tig + 8];
            af[3] = *(const uint32_t*)&Ps[lrow + 8][kk * 16 + 2 * tig + 8];
            #pragma unroll
            for (int nt = 0; nt < 8; nt++) {
                uint32_t bf[2];
                bf[0] = *(const uint32_t*)&Vt[nt * 8 + gid][kk * 16 + 2 * tig];
                bf[1] = *(const uint32_t*)&Vt[nt * 8 + gid][kk * 16 + 2 * tig + 8];
                mma_f16(oc[nt], af, bf);
            }
        }
    }

    const float i0 = 1.f / l0, i1 = 1.f / l1;
    #pragma unroll
    for (int nt = 0; nt < 8; nt++) {
        const int c = h * DH + nt * 8 + 2 * tig;
        *(__half2*)(g_Yh + (size_t)r0 * QC + c) =
            __floats2half2_rn(oc[nt][0] * i0, oc[nt][1] * i0);
        *(__half2*)(g_Yh + (size_t)r1 * QC + c) =
            __floats2half2_rn(oc[nt][2] * i1, oc[nt][3] * i1);
    }
}

// ---------------------------------------------------------------------------
extern "C" void kernel_launch(void* const* d_in, const int* in_sizes, int n_in,
                              void* d_out, int out_size)
{
    const float* x         = (const float*)d_in[0];
    const int*   positions = (const int*)  d_in[1];
    const float* Wq        = (const float*)d_in[2];
    const float* bq        = (const float*)d_in[3];
    const float* Wk        = (const float*)d_in[4];
    const float* bk        = (const float*)d_in[5];
    const float* Wv        = (const float*)d_in[6];
    const float* bv        = (const float*)d_in[7];
    const float* Wo        = (const float*)d_in[8];
    const float* bo        = (const float*)d_in[9];
    const int*   is_slide  = (const int*)  d_in[10];
    const int*   win       = (const int*)  d_in[11];

    cudaFuncSetAttribute(attn_mma, cudaFuncAttributeMaxDynamicSharedMemorySize, ATT_SMEM);
    cudaFuncSetAttribute(qkv_mma,  cudaFuncAttributeMaxDynamicSharedMemorySize, GEMM_SMEM);
    cudaFuncSetAttribute(out_mma,  cudaFuncAttributeMaxDynamicSharedMemorySize, GEMM_SMEM);

    dim3 tb(32, 8);
    conv_x<<<(TSEQ * HID / 4 + 255) / 256, 256>>>(x);
    transpose_qkv<<<dim3(NTOT / 32, HID / 32), tb>>>(Wq, Wk, Wv);
    transpose_wo <<<dim3(NOUT / 32, QC / 32),  tb>>>(Wo);

    qkv_mma<<<dim3(NTOT / 128, TSEQ / 128), 256, GEMM_SMEM>>>(positions, bq, bk, bv);

    attn_mma<<<dim3(TSEQ / 128, NHEAD), 256, ATT_SMEM>>>(is_slide, win);

    out_mma<<<dim3(NOUT_PAD / 128, TSEQ / 128), 256, GEMM_SMEM>>>(bo, (float*)d_out);
}

// round 7
// speedup vs baseline: 6.3228x; 1.0792x over previous
#include <cuda_runtime.h>
#include <cuda_fp16.h>
#include <math.h>
#include <stdint.h>

#define TSEQ 1536
#define HID  2880
#define NHEAD 64
#define NKVH  8
#define DH    64
#define QC   (NHEAD*DH)        /* 4096 */
#define KVC  (NKVH*DH)         /* 512  */
#define NTOT (QC + 2*KVC)      /* 5120 */
#define NOUT 2880
#define NOUT_PAD 2944          /* 23*128 */

#define L2THETA_OVER_32 0.53733134f

// ---------------- device-global scratch (zero-initialized) -------------------
__device__ __half g_Xh[(size_t)TSEQ*HID];
__device__ __half g_WTh[(size_t)NTOT*HID];     // qkv weights [n][k]
__device__ __half g_WoTh[(size_t)NOUT_PAD*QC]; // out weights [n][k], pad rows stay 0
__device__ __half g_Qh[(size_t)TSEQ*QC];
__device__ __half g_Kh[(size_t)TSEQ*KVC];
__device__ __half g_Vh[(size_t)TSEQ*KVC];
__device__ __half g_Yh[(size_t)TSEQ*QC];

// ---------------- helpers ----------------------------------------------------
__device__ __forceinline__ void mma_f16(float c[4], const uint32_t a[4], const uint32_t b[2]) {
    asm volatile(
        "mma.sync.aligned.m16n8k16.row.col.f32.f16.f16.f32 "
        "{%0,%1,%2,%3}, {%4,%5,%6,%7}, {%8,%9}, {%0,%1,%2,%3};"
        : "+f"(c[0]), "+f"(c[1]), "+f"(c[2]), "+f"(c[3])
        : "r"(a[0]), "r"(a[1]), "r"(a[2]), "r"(a[3]), "r"(b[0]), "r"(b[1]));
}
__device__ __forceinline__ void ldsm_x4(uint32_t r[4], uint32_t addr) {
    asm volatile("ldmatrix.sync.aligned.m8n8.x4.shared.b16 {%0,%1,%2,%3}, [%4];"
        : "=r"(r[0]), "=r"(r[1]), "=r"(r[2]), "=r"(r[3]) : "r"(addr));
}
__device__ __forceinline__ uint32_t smem_u32(const void* p) {
    uint32_t a;
    asm("{ .reg .u64 t; cvta.to.shared.u64 t, %1; cvt.u32.u64 %0, t; }" : "=r"(a) : "l"(p));
    return a;
}
__device__ __forceinline__ void cp16(uint32_t s, const void* g) {
    asm volatile("cp.async.cg.shared.global [%0], [%1], 16;" :: "r"(s), "l"(g));
}
#define CP_COMMIT() asm volatile("cp.async.commit_group;" ::: "memory")
#define CP_WAIT1()  asm volatile("cp.async.wait_group 1;" ::: "memory")

#define BK     32                      /* halves per k-chunk */
#define PAD_H  40                      /* halves per smem row; 80B = 5x16B -> LDSM conflict-free */
#define STAGE_BYTES (2*128*PAD_H*2)    /* A+B per stage = 20480 */
#define GEMM_SMEM   (3*STAGE_BYTES)    /* 61440 */

// ---------------- prep kernels -----------------------------------------------
__global__ void conv_x(const float* __restrict__ x)
{
    const size_t i = ((size_t)blockIdx.x * blockDim.x + threadIdx.x) * 4;
    if (i < (size_t)TSEQ * HID) {
        float4 v = *(const float4*)(x + i);
        __half2 h0 = __floats2half2_rn(v.x, v.y);
        __half2 h1 = __floats2half2_rn(v.z, v.w);
        *(uint2*)(g_Xh + i) = make_uint2(*(uint32_t*)&h0, *(uint32_t*)&h1);
    }
}

__global__ void transpose_qkv(const float* __restrict__ Wq,
                              const float* __restrict__ Wk,
                              const float* __restrict__ Wv)
{
    __shared__ float tile[32][33];
    const int n0 = blockIdx.x * 32, k0 = blockIdx.y * 32;
    const float* src; int ld, nb;
    if (n0 < QC)            { src = Wq; ld = QC;  nb = n0; }
    else if (n0 < QC + KVC) { src = Wk; ld = KVC; nb = n0 - QC; }
    else                    { src = Wv; ld = KVC; nb = n0 - QC - KVC; }
    const int tx = threadIdx.x, ty = threadIdx.y;
    #pragma unroll
    for (int i = 0; i < 32; i += 8)
        tile[ty + i][tx] = src[(size_t)(k0 + ty + i) * ld + nb + tx];
    __syncthreads();
    #pragma unroll
    for (int i = 0; i < 32; i += 8)
        g_WTh[(size_t)(n0 + ty + i) * HID + k0 + tx] = __float2half_rn(tile[tx][ty + i]);
}

__global__ void transpose_wo(const float* __restrict__ Wo)
{
    __shared__ float tile[32][33];
    const int n0 = blockIdx.x * 32, k0 = blockIdx.y * 32;
    const int tx = threadIdx.x, ty = threadIdx.y;
    #pragma unroll
    for (int i = 0; i < 32; i += 8)
        tile[ty + i][tx] = Wo[(size_t)(k0 + ty + i) * NOUT + n0 + tx];
    __syncthreads();
    #pragma unroll
    for (int i = 0; i < 32; i += 8)
        g_WoTh[(size_t)(n0 + ty + i) * QC + k0 + tx] = __float2half_rn(tile[tx][ty + i]);
}

// ---------------- GEMM mainloop: cp.async 3-stage + ldmatrix + fp16 mma ------
__device__ __forceinline__ void gemm_mainloop_f16(
    const __half* __restrict__ Ag, const __half* __restrict__ Bg,
    int m0, int n0, int K,
    float (&acc)[2][8][4], char* sm)
{
    const int tid  = threadIdx.x;
    const int lane = tid & 31;
    const int wid  = tid >> 5;
    const int warp_m = wid & 3, warp_n = wid >> 2;
    const uint32_t sbase = smem_u32(sm);

    // ldmatrix lane address components
    const int a_row = warp_m * 32 + (lane & 15);         // + mt*16
    const int a_col = (lane >> 4) << 3;                  // + ks
    const int b_row = warp_n * 64 + ((lane >> 4) << 3) + (lane & 7);  // + p*16
    const int b_col = ((lane >> 3) & 1) << 3;            // + ks

    // loader: 128 rows x 4 chunks(8 halves) per matrix; 256 thr -> 2 each
    int rr_[2], ff_[2];
    #pragma unroll
    for (int i = 0; i < 2; i++) {
        int idx = i * 256 + tid;
        rr_[i] = idx >> 2;
        ff_[i] = (idx & 3) * 8;
    }

    const int NK = K / BK;

    #define ISSUE(s, kc) do { \
        const uint32_t a_s = sbase + (s) * STAGE_BYTES; \
        const uint32_t b_s = a_s + 128 * PAD_H * 2; \
        const int kof = (kc) * BK; \
        _Pragma("unroll") \
        for (int i = 0; i < 2; i++) { \
            cp16(a_s + (rr_[i] * PAD_H + ff_[i]) * 2, Ag + (size_t)(m0 + rr_[i]) * K + kof + ff_[i]); \
            cp16(b_s + (rr_[i] * PAD_H + ff_[i]) * 2, Bg + (size_t)(n0 + rr_[i]) * K + kof + ff_[i]); \
        } \
        CP_COMMIT(); \
    } while (0)

    ISSUE(0, 0);
    ISSUE(1, 1);

    for (int kc = 0; kc < NK; kc++) {
        CP_WAIT1();
        __syncthreads();
        if (kc + 2 < NK) ISSUE((kc + 2) % 3, kc + 2);
        else             CP_COMMIT();

        const uint32_t as_b = sbase + (kc % 3) * STAGE_BYTES;
        const uint32_t bs_b = as_b + 128 * PAD_H * 2;

        #pragma unroll
        for (int ks = 0; ks < BK; ks += 16) {
            uint32_t af[2][4], bf[16];
            #pragma unroll
            for (int mt = 0; mt < 2; mt++)
                ldsm_x4(af[mt], as_b + (((a_row + mt * 16) * PAD_H) + ks + a_col) * 2);
            #pragma unroll
            for (int p = 0; p < 4; p++)
                ldsm_x4(&bf[4 * p], bs_b + (((b_row + p * 16) * PAD_H) + ks + b_col) * 2);
            #pragma unroll
            for (int mt = 0; mt < 2; mt++)
                #pragma unroll
                for (int nt = 0; nt < 8; nt++)
                    mma_f16(acc[mt][nt], af[mt], &bf[(nt >> 1) * 4 + (nt & 1) * 2]);
        }
    }
    #undef ISSUE
}

// ---------------- QKV projection (+bias, +RoPE) ------------------------------
__global__ __launch_bounds__(256) void qkv_mma(
    const int* __restrict__ positions,
    const float* __restrict__ bq, const float* __restrict__ bk,
    const float* __restrict__ bv)
{
    extern __shared__ char sm[];
    const int tid  = threadIdx.x;
    const int lane = tid & 31;
    const int wid  = tid >> 5;
    const int warp_m = wid & 3, warp_n = wid >> 2;
    const int gid = lane >> 2, tig = lane & 3;
    const int m0 = blockIdx.y * 128, n0 = blockIdx.x * 128;

    const float* bias; __half* outp; int ldout, nloc0, do_rope;
    if (n0 < QC)            { bias = bq; outp = g_Qh; ldout = QC;  nloc0 = n0;            do_rope = 1; }
    else if (n0 < QC + KVC) { bias = bk; outp = g_Kh; ldout = KVC; nloc0 = n0 - QC;       do_rope = 1; }
    else                    { bias = bv; outp = g_Vh; ldout = KVC; nloc0 = n0 - QC - KVC; do_rope = 0; }

    float acc[2][8][4];
    #pragma unroll
    for (int a = 0; a < 2; a++)
        #pragma unroll
        for (int b = 0; b < 8; b++)
            #pragma unroll
            for (int d = 0; d < 4; d++) acc[a][b][d] = 0.f;

    gemm_mainloop_f16(g_Xh, g_WTh, m0, n0, HID, acc, sm);

    #pragma unroll
    for (int mt = 0; mt < 2; mt++) {
        const int t_lo = m0 + warp_m * 32 + mt * 16 + gid;
        const int t_hi = t_lo + 8;
        float pos_lo = 0.f, pos_hi = 0.f;
        if (do_rope) { pos_lo = (float)positions[t_lo]; pos_hi = (float)positions[t_hi]; }
        #pragma unroll
        for (int nt = 0; nt < 8; nt++) {
            const int c = nloc0 + warp_n * 64 + nt * 8 + 2 * tig;
            const float b0 = bias[c], b1 = bias[c + 1];
            float v0 = acc[mt][nt][0] + b0, v1 = acc[mt][nt][1] + b1;
            float v2 = acc[mt][nt][2] + b0, v3 = acc[mt][nt][3] + b1;
            if (do_rope) {
                const int ip = (c & (DH - 1)) >> 1;
                const float inv_eff = 0.515625f * exp2f(-(float)ip * L2THETA_OVER_32);
                float s, co;
                __sincosf(pos_lo * (1.0f / 32.0f) * inv_eff, &s, &co);
                float e = v0 * co - v1 * s; v1 = v0 * s + v1 * co; v0 = e;
                __sincosf(pos_hi * (1.0f / 32.0f) * inv_eff, &s, &co);
                e = v2 * co - v3 * s; v3 = v2 * s + v3 * co; v2 = e;
            }
            *(__half2*)(outp + (size_t)t_lo * ldout + c) = __floats2half2_rn(v0, v1);
            *(__half2*)(outp + (size_t)t_hi * ldout + c) = __floats2half2_rn(v2, v3);
        }
    }
}

// ---------------- output projection (+bias) ----------------------------------
__global__ __launch_bounds__(256) void out_mma(
    const float* __restrict__ bo, float* __restrict__ out)
{
    extern __shared__ char sm[];
    const int tid  = threadIdx.x;
    const int lane = tid & 31;
    const int wid  = tid >> 5;
    const int warp_m = wid & 3, warp_n = wid >> 2;
    const int gid = lane >> 2, tig = lane & 3;
    const int m0 = blockIdx.y * 128, n0 = blockIdx.x * 128;

    float acc[2][8][4];
    #pragma unroll
    for (int a = 0; a < 2; a++)
        #pragma unroll
        for (int b = 0; b < 8; b++)
            #pragma unroll
            for (int d = 0; d < 4; d++) acc[a][b][d] = 0.f;

    gemm_mainloop_f16(g_Yh, g_WoTh, m0, n0, QC, acc, sm);

    #pragma unroll
    for (int mt = 0; mt < 2; mt++) {
        const int t_lo = m0 + warp_m * 32 + mt * 16 + gid;
        const int t_hi = t_lo + 8;
        #pragma unroll
        for (int nt = 0; nt < 8; nt++) {
            const int c = n0 + warp_n * 64 + nt * 8 + 2 * tig;
            if (c < NOUT) {
                const float b0 = bo[c], b1 = bo[c + 1];
                *(float2*)(out + (size_t)t_lo * NOUT + c) =
                    make_float2(acc[mt][nt][0] + b0, acc[mt][nt][1] + b1);
                *(float2*)(out + (size_t)t_hi * NOUT + c) =
                    make_float2(acc[mt][nt][2] + b0, acc[mt][nt][3] + b1);
            }
        }
    }
}

// ---------------- tensor-core flash attention (fp16 mma + ldmatrix) ----------
#define KS_H 72    /* 144B = 9x16B  -> LDSM conflict-free */
#define VT_H 136   /* 272B = 17x16B -> LDSM conflict-free */
#define PS_H 136
#define OFF_VT (128*KS_H*2)
#define OFF_PS (OFF_VT + 64*VT_H*2)
#define ATT_SMEM (OFF_PS + 128*PS_H*2)   /* 70656 */

__global__ __launch_bounds__(256) void attn_mma(
    const int* __restrict__ is_slide_p, const int* __restrict__ win_p)
{
    extern __shared__ char sm[];
    __half (*Ks)[KS_H] = (__half(*)[KS_H])(sm);
    __half (*Vt)[VT_H] = (__half(*)[VT_H])(sm + OFF_VT);
    __half (*Ps)[PS_H] = (__half(*)[PS_H])(sm + OFF_PS);
    const uint32_t ks_b = smem_u32(sm);
    const uint32_t vt_b = ks_b + OFF_VT;
    const uint32_t ps_b = ks_b + OFF_PS;

    const int tid = threadIdx.x, lane = tid & 31, wid = tid >> 5;
    const int gid = lane >> 2, tig = lane & 3;
    const int t0 = blockIdx.x * 128, h = blockIdx.y, kvh = h >> 3;
    const int is_slide = is_slide_p[0], W = win_p[0];

    const int r0 = t0 + wid * 16 + gid, r1 = r0 + 8;
    const int rlo0 = is_slide ? r0 - W : 0;
    const int rlo1 = is_slide ? r1 - W : 0;
    const int lrow = wid * 16 + gid;

    // ldmatrix address components
    const int ld_row16 = lane & 15;                      // rows within 16
    const int ld_koff  = (lane >> 4) << 3;               // k offset 0/8
    const int ld_nrow  = ((lane >> 4) << 3) + (lane & 7);// B n-row within 16
    const int ld_bkoff = ((lane >> 3) & 1) << 3;         // B k offset 0/8

    // Q fragments (4 k16 steps over DH=64)
    uint32_t qf[4][4];
    {
        const __half* q0 = g_Qh + (size_t)r0 * QC + h * DH;
        const __half* q1 = g_Qh + (size_t)r1 * QC + h * DH;
        #pragma unroll
        for (int kk = 0; kk < 4; kk++) {
            qf[kk][0] = *(const uint32_t*)(q0 + kk * 16 + 2 * tig);
            qf[kk][1] = *(const uint32_t*)(q1 + kk * 16 + 2 * tig);
            qf[kk][2] = *(const uint32_t*)(q0 + kk * 16 + 2 * tig + 8);
            qf[kk][3] = *(const uint32_t*)(q1 + kk * 16 + 2 * tig + 8);
        }
    }

    float oc[8][4];
    #pragma unroll
    for (int nt = 0; nt < 8; nt++)
        #pragma unroll
        for (int d = 0; d < 4; d++) oc[nt][d] = 0.f;
    float m0v = -1e30f, m1v = -1e30f, l0 = 0.f, l1 = 0.f;

    const int cs0 = is_slide ? (max(0, t0 - W) & ~127) : 0;

    for (int cs = cs0; cs <= t0; cs += 128) {
        __syncthreads();
        #pragma unroll
        for (int i = 0; i < 4; i++) {
            int idx = i * 256 + tid, rr = idx >> 3, c8 = (idx & 7) * 8;
            *(uint4*)&Ks[rr][c8] =
                *(const uint4*)(g_Kh + (size_t)(cs + rr) * KVC + kvh * DH + c8);
            union { uint4 u; __half hv[8]; } v;
            v.u = *(const uint4*)(g_Vh + (size_t)(cs + rr) * KVC + kvh * DH + c8);
            #pragma unroll
            for (int j = 0; j < 8; j++) Vt[c8 + j][rr] = v.hv[j];
        }
        __syncthreads();

        // S = Q @ K^T : 8 n-pairs x 4 k-steps, B frags via ldmatrix
        float sc[16][4];
        #pragma unroll
        for (int p = 0; p < 8; p++) {
            sc[2*p][0] = sc[2*p][1] = sc[2*p][2] = sc[2*p][3] = 0.f;
            sc[2*p+1][0] = sc[2*p+1][1] = sc[2*p+1][2] = sc[2*p+1][3] = 0.f;
            #pragma unroll
            for (int kk = 0; kk < 4; kk++) {
                uint32_t bf[4];
                ldsm_x4(bf, ks_b + (((p * 16 + ld_nrow) * KS_H) + kk * 16 + ld_bkoff) * 2);
                mma_f16(sc[2*p],     qf[kk], &bf[0]);
                mma_f16(sc[2*p + 1], qf[kk], &bf[2]);
            }
        }

        // scale + mask + online softmax
        float vmax0 = -1e30f, vmax1 = -1e30f;
        #pragma unroll
        for (int nt = 0; nt < 16; nt++) {
            const int s0 = cs + nt * 8 + 2 * tig, s1 = s0 + 1;
            float v0 = (s0 <= r0 && s0 >= rlo0) ? sc[nt][0] * 0.125f : -1e30f;
            float v1 = (s1 <= r0 && s1 >= rlo0) ? sc[nt][1] * 0.125f : -1e30f;
            float v2 = (s0 <= r1 && s0 >= rlo1) ? sc[nt][2] * 0.125f : -1e30f;
            float v3 = (s1 <= r1 && s1 >= rlo1) ? sc[nt][3] * 0.125f : -1e30f;
            sc[nt][0] = v0; sc[nt][1] = v1; sc[nt][2] = v2; sc[nt][3] = v3;
            vmax0 = fmaxf(vmax0, fmaxf(v0, v1));
            vmax1 = fmaxf(vmax1, fmaxf(v2, v3));
        }
        vmax0 = fmaxf(vmax0, __shfl_xor_sync(0xffffffffu, vmax0, 1));
        vmax0 = fmaxf(vmax0, __shfl_xor_sync(0xffffffffu, vmax0, 2));
        vmax1 = fmaxf(vmax1, __shfl_xor_sync(0xffffffffu, vmax1, 1));
        vmax1 = fmaxf(vmax1, __shfl_xor_sync(0xffffffffu, vmax1, 2));

        const float mn0 = fmaxf(m0v, vmax0), mn1 = fmaxf(m1v, vmax1);
        const float a0 = __expf(m0v - mn0), a1 = __expf(m1v - mn1);
        m0v = mn0; m1v = mn1;

        float ps0 = 0.f, ps1 = 0.f;
        #pragma unroll
        for (int nt = 0; nt < 16; nt++) {
            float p0 = __expf(sc[nt][0] - mn0), p1 = __expf(sc[nt][1] - mn0);
            float p2 = __expf(sc[nt][2] - mn1), p3 = __expf(sc[nt][3] - mn1);
            ps0 += p0 + p1; ps1 += p2 + p3;
            *(__half2*)&Ps[lrow][nt * 8 + 2 * tig] = __floats2half2_rn(p0, p1);
            *(__half2*)&Ps[lrow + 8][nt * 8 + 2 * tig] = __floats2half2_rn(p2, p3);
        }
        ps0 += __shfl_xor_sync(0xffffffffu, ps0, 1);
        ps0 += __shfl_xor_sync(0xffffffffu, ps0, 2);
        ps1 += __shfl_xor_sync(0xffffffffu, ps1, 1);
        ps1 += __shfl_xor_sync(0xffffffffu, ps1, 2);
        l0 = l0 * a0 + ps0;
        l1 = l1 * a1 + ps1;

        #pragma unroll
        for (int nt = 0; nt < 8; nt++) {
            oc[nt][0] *= a0; oc[nt][1] *= a0;
            oc[nt][2] *= a1; oc[nt][3] *= a1;
        }
        __syncwarp();

        // O += P @ V : per k16 step, A frag 1 ldmatrix + B frags 4 ldmatrix
        #pragma unroll
        for (int kk = 0; kk < 8; kk++) {
            uint32_t af[4];
            ldsm_x4(af, ps_b + (((wid * 16 + ld_row16) * PS_H) + kk * 16 + ld_koff) * 2);
            #pragma unroll
            for (int p = 0; p < 4; p++) {
                uint32_t bf[4];
                ldsm_x4(bf, vt_b + (((p * 16 + ld_nrow) * VT_H) + kk * 16 + ld_bkoff) * 2);
                mma_f16(oc[2*p],     af, &bf[0]);
                mma_f16(oc[2*p + 1], af, &bf[2]);
            }
        }
    }

    const float i0 = 1.f / l0, i1 = 1.f / l1;
    #pragma unroll
    for (int nt = 0; nt < 8; nt++) {
        const int c = h * DH + nt * 8 + 2 * tig;
        *(__half2*)(g_Yh + (size_t)r0 * QC + c) =
            __floats2half2_rn(oc[nt][0] * i0, oc[nt][1] * i0);
        *(__half2*)(g_Yh + (size_t)r1 * QC + c) =
            __floats2half2_rn(oc[nt][2] * i1, oc[nt][3] * i1);
    }
}

// ---------------------------------------------------------------------------
extern "C" void kernel_launch(void* const* d_in, const int* in_sizes, int n_in,
                              void* d_out, int out_size)
{
    const float* x         = (const float*)d_in[0];
    const int*   positions = (const int*)  d_in[1];
    const float* Wq        = (const float*)d_in[2];
    const float* bq        = (const float*)d_in[3];
    const float* Wk        = (const float*)d_in[4];
    const float* bk        = (const float*)d_in[5];
    const float* Wv        = (const float*)d_in[6];
    const float* bv        = (const float*)d_in[7];
    const float* Wo        = (const float*)d_in[8];
    const float* bo        = (const float*)d_in[9];
    const int*   is_slide  = (const int*)  d_in[10];
    const int*   win       = (const int*)  d_in[11];

    cudaFuncSetAttribute(attn_mma, cudaFuncAttributeMaxDynamicSharedMemorySize, ATT_SMEM);
    cudaFuncSetAttribute(qkv_mma,  cudaFuncAttributeMaxDynamicSharedMemorySize, GEMM_SMEM);
    cudaFuncSetAttribute(out_mma,  cudaFuncAttributeMaxDynamicSharedMemorySize, GEMM_SMEM);

    dim3 tb(32, 8);
    conv_x<<<(TSEQ * HID / 4 + 255) / 256, 256>>>(x);
    transpose_qkv<<<dim3(NTOT / 32, HID / 32), tb>>>(Wq, Wk, Wv);
    transpose_wo <<<dim3(NOUT / 32, QC / 32),  tb>>>(Wo);

    qkv_mma<<<dim3(NTOT / 128, TSEQ / 128), 256, GEMM_SMEM>>>(positions, bq, bk, bv);

    attn_mma<<<dim3(TSEQ / 128, NHEAD), 256, ATT_SMEM>>>(is_slide, win);

    out_mma<<<dim3(NOUT_PAD / 128, TSEQ / 128), 256, GEMM_SMEM>>>(bo, (float*)d_out);
}